// round 8
// baseline (speedup 1.0000x reference)
#include <cuda_runtime.h>
#include <cuda_bf16.h>
#include <cstdint>
#include <math.h>

#define BATCH 8
#define GH 64
#define GW 64
#define NNODE 4096
#define CCH 512
#define MROWS (BATCH * NNODE)
#define EPSV 1e-5f

// ---------------- scratch ----------------
__device__ float g_res[MROWS * CCH];
__device__ float g_t[MROWS * CCH];
__device__ __nv_bfloat16 g_ah[MROWS * CCH];
__device__ __nv_bfloat16 g_al[MROWS * CCH];
__device__ __nv_bfloat16 g_wh[4 * CCH * CCH];
__device__ __nv_bfloat16 g_wl[4 * CCH * CCH];
__device__ float g_hp[256 * CCH];
__device__ float g_rs[256 * CCH];
__device__ float g_rq[256 * CCH];
__device__ float g_xg[BATCH * CCH];
__device__ float g_scale[CCH];
__device__ float g_shift[CCH];

// ---------------- helpers ----------------
__device__ __forceinline__ uint32_t smem_u32(const void* p) {
    uint32_t a;
    asm("{ .reg .u64 t; cvta.to.shared.u64 t, %1; cvt.u32.u64 %0, t; }" : "=r"(a) : "l"(p));
    return a;
}
__device__ __forceinline__ void ldsm_x4(uint32_t addr, uint32_t* r) {
    asm volatile("ldmatrix.sync.aligned.m8n8.x4.shared.b16 {%0,%1,%2,%3}, [%4];"
                 : "=r"(r[0]), "=r"(r[1]), "=r"(r[2]), "=r"(r[3]) : "r"(addr));
}
__device__ __forceinline__ void mma16816(float* c, const uint32_t* a, const uint32_t* b) {
    asm volatile("mma.sync.aligned.m16n8k16.row.col.f32.bf16.bf16.f32 "
                 "{%0,%1,%2,%3}, {%4,%5,%6,%7}, {%8,%9}, {%0,%1,%2,%3};"
                 : "+f"(c[0]), "+f"(c[1]), "+f"(c[2]), "+f"(c[3])
                 : "r"(a[0]), "r"(a[1]), "r"(a[2]), "r"(a[3]), "r"(b[0]), "r"(b[1]));
}
__device__ __forceinline__ void cp16(uint32_t dst, const void* src) {
    asm volatile("cp.async.cg.shared.global [%0], [%1], 16;" :: "r"(dst), "l"(src) : "memory");
}
#define CP_COMMIT() asm volatile("cp.async.commit_group;" ::: "memory")
#define CP_WAIT0()  asm volatile("cp.async.wait_group 0;" ::: "memory")
#define CP_WAIT1()  asm volatile("cp.async.wait_group 1;" ::: "memory")

__device__ __forceinline__ uint32_t pk_hi(float x, float y, float& rx, float& ry) {
    __nv_bfloat16 hx = __float2bfloat16(x), hy = __float2bfloat16(y);
    rx = x - __bfloat162float(hx);
    ry = y - __bfloat162float(hy);
    return (uint32_t)__bfloat16_as_ushort(hx) | ((uint32_t)__bfloat16_as_ushort(hy) << 16);
}
__device__ __forceinline__ uint32_t pk(float x, float y) {
    return (uint32_t)__bfloat16_as_ushort(__float2bfloat16(x))
         | ((uint32_t)__bfloat16_as_ushort(__float2bfloat16(y)) << 16);
}

// ---------------- mma.sync split-bf16 GEMM, 128x64 CTA tile, 3-stage SW128 -----
// A row (128B) = [Ah 32 bf16 | Al 32 bf16], chunk16 j at (j ^ (row&7)).
// Stage = A 16KB + B 8KB = 24KB; 3 stages. bf16 path: 3 CTAs/SM (24 warps).
// mode bits: 1=store C, 2=relu, 4=bias, 8=column-sum partials, 16=also sumsq
#define ATILE 16384u
#define BTILE 8192u
#define STAGEB 24576u
#define GEMM_SMEM (3u * STAGEB)

template<int AFP32>
__global__ __launch_bounds__(256, AFP32 ? 2 : 3)
void gemm_mma(const void* __restrict__ A0, const void* __restrict__ A1,
              const __nv_bfloat16* __restrict__ Bh, const __nv_bfloat16* __restrict__ Bl,
              float* __restrict__ C0, float* __restrict__ C1,
              const float* __restrict__ bias0, const float* __restrict__ bias1,
              float* __restrict__ redS, float* __restrict__ redQ,
              int mode0, int mode1)
{
    extern __shared__ __align__(128) char smem[];
    const uint32_t sb = smem_u32(smem);
    const int tid = threadIdx.x;
    const int wid = tid >> 5;
    const int lane = tid & 31;
    const int wm = wid & 3;       // M quarter (32 rows)
    const int wn = wid >> 2;      // N half (32 cols)
    const int mtile = blockIdx.y;
    const int ntile = blockIdx.x;

    const __nv_bfloat16* src0 = (const __nv_bfloat16*)A0 + (size_t)mtile * 128 * 512;
    const __nv_bfloat16* src1 = (const __nv_bfloat16*)A1 + (size_t)mtile * 128 * 512;
    const float* srcx = (const float*)A0 + (size_t)mtile * 128 * 512;
    const __nv_bfloat16* src2 = Bh + (size_t)ntile * 64 * 512;
    const __nv_bfloat16* src3 = Bl + (size_t)ntile * 64 * 512;

    float acc[2][4][4];
    #pragma unroll
    for (int i = 0; i < 2; i++)
        #pragma unroll
        for (int j = 0; j < 4; j++)
            #pragma unroll
            for (int k = 0; k < 4; k++) acc[i][j][k] = 0.f;

    const int lr = lane & 15;
    const int lk = lane >> 4;
    const int bn = (lane & 7) + ((lane >> 4) << 3);
    const int bkc2 = (lane >> 3) & 1;

    const int au_row[2] = { tid >> 2, (256 + tid) >> 2 };
    const int au_ch = tid & 3;
    float4 ra[2][2];

    // bf16 path: full stage (A 1024 + B 512 chunks = 6/thread)
    #define LOAD_STAGE_BF16(kc, st) do { \
        const int _kc = (kc); const uint32_t _b = sb + (uint32_t)(st) * STAGEB; \
        _Pragma("unroll") \
        for (int p = 0; p < 6; p++) { \
            const int id = p * 256 + tid; \
            const int isB = id >> 10; \
            const int e = id & 1023; \
            const int row = e >> 3, j = e & 7; \
            const uint32_t dst = _b + (uint32_t)isB * ATILE + (uint32_t)row * 128u \
                               + (uint32_t)((j ^ (row & 7)) << 4); \
            const __nv_bfloat16* s = (isB == 0 ? (j < 4 ? src0 : src1) : (j < 4 ? src2 : src3)) \
                                     + (size_t)row * 512 + (size_t)_kc * 32 + (j & 3) * 8; \
            cp16(dst, s); \
        } \
        CP_COMMIT(); \
    } while (0)

    // fp32 path: B-only stage (512 chunks = 2/thread)
    #define LOAD_STAGE_B(kc, st) do { \
        const int _kc = (kc); const uint32_t _b = sb + (uint32_t)(st) * STAGEB + ATILE; \
        _Pragma("unroll") \
        for (int p = 0; p < 2; p++) { \
            const int id = p * 256 + tid; \
            const int row = id >> 3, j = id & 7; \
            const uint32_t dst = _b + (uint32_t)row * 128u + (uint32_t)((j ^ (row & 7)) << 4); \
            const __nv_bfloat16* s = (j < 4 ? src2 : src3) \
                                     + (size_t)row * 512 + (size_t)_kc * 32 + (j & 3) * 8; \
            cp16(dst, s); \
        } \
        CP_COMMIT(); \
    } while (0)

    #define LOAD_A_F32(kc) do { \
        const int _kc = (kc); \
        _Pragma("unroll") \
        for (int i = 0; i < 2; i++) { \
            const float* s = srcx + (size_t)au_row[i] * 512 + (size_t)_kc * 32 + au_ch * 8; \
            ra[i][0] = *(const float4*)s; \
            ra[i][1] = *(const float4*)(s + 4); \
        } \
    } while (0)

    #define STORE_A_F32(st) do { \
        const uint32_t _o = (uint32_t)(st) * STAGEB; \
        _Pragma("unroll") \
        for (int i = 0; i < 2; i++) { \
            float r0, r1, r2, r3, r4, r5, r6, r7; \
            uint4 hi, lo; \
            hi.x = pk_hi(ra[i][0].x, ra[i][0].y, r0, r1); \
            hi.y = pk_hi(ra[i][0].z, ra[i][0].w, r2, r3); \
            hi.z = pk_hi(ra[i][1].x, ra[i][1].y, r4, r5); \
            hi.w = pk_hi(ra[i][1].z, ra[i][1].w, r6, r7); \
            lo.x = pk(r0, r1); lo.y = pk(r2, r3); lo.z = pk(r4, r5); lo.w = pk(r6, r7); \
            const int sw = au_row[i] & 7; \
            *(uint4*)(smem + _o + (uint32_t)au_row[i] * 128u + (uint32_t)((au_ch ^ sw) << 4)) = hi; \
            *(uint4*)(smem + _o + (uint32_t)au_row[i] * 128u + (uint32_t)(((au_ch + 4) ^ sw) << 4)) = lo; \
        } \
    } while (0)

    if (AFP32) {
        LOAD_A_F32(0); STORE_A_F32(0);
        LOAD_STAGE_B(0, 0);
        LOAD_STAGE_B(1, 1);
    } else {
        LOAD_STAGE_BF16(0, 0);
        LOAD_STAGE_BF16(1, 1);
    }

    #pragma unroll 1
    for (int kc = 0; kc < 16; kc++) {
        if (kc < 15) { CP_WAIT1(); } else { CP_WAIT0(); }
        __syncthreads();
        const int st = kc % 3;
        if (kc + 2 < 16) {
            const int st2 = (kc + 2) % 3;
            if (AFP32) LOAD_STAGE_B(kc + 2, st2);
            else       LOAD_STAGE_BF16(kc + 2, st2);
        }
        if (AFP32 && kc + 1 < 16) LOAD_A_F32(kc + 1);

        const uint32_t baseA = sb + (uint32_t)st * STAGEB;
        const uint32_t baseB = baseA + ATILE;
        #pragma unroll
        for (int ks = 0; ks < 2; ks++) {
            uint32_t ah[2][4], al[2][4];
            #pragma unroll
            for (int mi = 0; mi < 2; mi++) {
                const int R = wm * 32 + mi * 16 + lr;
                const int sw = R & 7;
                const int ch = 2 * ks + lk;
                ldsm_x4(baseA + (uint32_t)R * 128u + (uint32_t)((ch ^ sw) << 4), ah[mi]);
                ldsm_x4(baseA + (uint32_t)R * 128u + (uint32_t)(((ch + 4) ^ sw) << 4), al[mi]);
            }
            #pragma unroll
            for (int np = 0; np < 2; np++) {
                uint32_t bh[2][2], bl[2][2];
                const int R = wn * 32 + np * 16 + bn;
                const int sw = R & 7;
                const int ch = 2 * ks + bkc2;
                uint32_t r[4];
                ldsm_x4(baseB + (uint32_t)R * 128u + (uint32_t)((ch ^ sw) << 4), r);
                bh[0][0] = r[0]; bh[0][1] = r[1]; bh[1][0] = r[2]; bh[1][1] = r[3];
                ldsm_x4(baseB + (uint32_t)R * 128u + (uint32_t)(((ch + 4) ^ sw) << 4), r);
                bl[0][0] = r[0]; bl[0][1] = r[1]; bl[1][0] = r[2]; bl[1][1] = r[3];
                #pragma unroll
                for (int mi = 0; mi < 2; mi++)
                    #pragma unroll
                    for (int b2 = 0; b2 < 2; b2++) {
                        const int nb = np * 2 + b2;
                        mma16816(acc[mi][nb], ah[mi], bh[b2]);
                        mma16816(acc[mi][nb], ah[mi], bl[b2]);
                        mma16816(acc[mi][nb], al[mi], bh[b2]);
                    }
            }
        }
        if (AFP32 && kc + 1 < 16) STORE_A_F32((kc + 1) % 3);
    }

    // ---------------- epilogue ----------------
    const int selc = ntile >> 3;
    const int mode = selc ? mode1 : mode0;
    const float* bias = selc ? bias1 : bias0;
    float* C = selc ? C1 : C0;
    const int ncol = (ntile & 7) * 64;

    const int gid = lane >> 2;
    const int tig = lane & 3;

    float rsum[4][2], rq[4][2];
    #pragma unroll
    for (int nb = 0; nb < 4; nb++) { rsum[nb][0] = rsum[nb][1] = rq[nb][0] = rq[nb][1] = 0.f; }

    #pragma unroll
    for (int mi = 0; mi < 2; mi++) {
        const int row0 = mtile * 128 + wm * 32 + mi * 16 + gid;
        #pragma unroll
        for (int nb = 0; nb < 4; nb++) {
            const int col = ncol + wn * 32 + nb * 8 + tig * 2;
            float b0 = 0.f, b1 = 0.f;
            if (mode & 4) { b0 = __ldg(bias + col); b1 = __ldg(bias + col + 1); }
            float v0 = acc[mi][nb][0] + b0, v1 = acc[mi][nb][1] + b1;
            float v2 = acc[mi][nb][2] + b0, v3 = acc[mi][nb][3] + b1;
            if (mode & 2) {
                v0 = fmaxf(v0, 0.f); v1 = fmaxf(v1, 0.f);
                v2 = fmaxf(v2, 0.f); v3 = fmaxf(v3, 0.f);
            }
            if (mode & 1) {
                *(float2*)(C + (size_t)row0 * 512 + col) = make_float2(v0, v1);
                *(float2*)(C + (size_t)(row0 + 8) * 512 + col) = make_float2(v2, v3);
            }
            if (mode & 8) {
                rsum[nb][0] += v0 + v2; rsum[nb][1] += v1 + v3;
                if (mode & 16) {
                    rq[nb][0] = fmaf(v0, v0, fmaf(v2, v2, rq[nb][0]));
                    rq[nb][1] = fmaf(v1, v1, fmaf(v3, v3, rq[nb][1]));
                }
            }
        }
    }

    if (mode & 8) {
        #pragma unroll
        for (int nb = 0; nb < 4; nb++)
            #pragma unroll
            for (int j = 0; j < 2; j++) {
                #pragma unroll
                for (int m = 4; m <= 16; m <<= 1) {
                    rsum[nb][j] += __shfl_xor_sync(0xffffffffu, rsum[nb][j], m);
                    rq[nb][j]   += __shfl_xor_sync(0xffffffffu, rq[nb][j], m);
                }
            }
        __syncthreads();
        float* red = (float*)smem;   // [wm(4)][64] sums, +256: sumsq
        if (gid == 0) {
            #pragma unroll
            for (int nb = 0; nb < 4; nb++) {
                const int cc = wn * 32 + nb * 8 + tig * 2;
                red[wm * 64 + cc]     = rsum[nb][0];
                red[wm * 64 + cc + 1] = rsum[nb][1];
                red[256 + wm * 64 + cc]     = rq[nb][0];
                red[256 + wm * 64 + cc + 1] = rq[nb][1];
            }
        }
        __syncthreads();
        if (tid < 64) {
            const float s = red[tid] + red[64 + tid] + red[128 + tid] + red[192 + tid];
            redS[(size_t)mtile * 512 + ncol + tid] = s;
            if (mode & 16) {
                const float q = red[256 + tid] + red[320 + tid] + red[384 + tid] + red[448 + tid];
                redQ[(size_t)mtile * 512 + ncol + tid] = q;
            }
        }
    }
}

// ---------------- convert+transpose weights ----------------
__global__ void convert_w_kernel(const float* __restrict__ w0, const float* __restrict__ w1,
                                 const float* __restrict__ w2, const float* __restrict__ w3,
                                 __nv_bfloat16* __restrict__ wh, __nv_bfloat16* __restrict__ wl)
{
    __shared__ float t[32][33];
    const int wsel = blockIdx.z;
    const float* w = wsel == 0 ? w0 : wsel == 1 ? w1 : wsel == 2 ? w2 : w3;
    __nv_bfloat16* oh = wh + (size_t)wsel * CCH * CCH;
    __nv_bfloat16* ol = wl + (size_t)wsel * CCH * CCH;
    const int n0 = blockIdx.x * 32;
    const int k0 = blockIdx.y * 32;
    const int tx = threadIdx.x, ty = threadIdx.y;
    #pragma unroll
    for (int j = 0; j < 4; j++)
        t[ty + j * 8][tx] = w[(size_t)(k0 + ty + j * 8) * 512 + n0 + tx];
    __syncthreads();
    #pragma unroll
    for (int j = 0; j < 4; j++) {
        const float v = t[tx][ty + j * 8];
        const __nv_bfloat16 hb = __float2bfloat16(v);
        oh[(size_t)(n0 + ty + j * 8) * 512 + k0 + tx] = hb;
        ol[(size_t)(n0 + ty + j * 8) * 512 + k0 + tx] = __float2bfloat16(v - __bfloat162float(hb));
    }
}

// ---------------- GCN aggregation ----------------
__device__ __forceinline__ float degf(int r, int c) {
    return 1.f + (float)(c > 0) + (float)(c < GW - 1) + (float)(r > 0) + (float)(r < GH - 1);
}

__global__ void agg_split_kernel(const float* __restrict__ in,
                                 __nv_bfloat16* __restrict__ oh, __nv_bfloat16* __restrict__ ol)
{
    const int idx = blockIdx.x * 256 + threadIdx.x;
    const int c4 = idx & 127;
    const int node = (idx >> 7) & (NNODE - 1);
    const int b = idx >> 19;
    const int r = node >> 6;
    const int cc = node & 63;

    const float4* base = (const float4*)in + (size_t)b * NNODE * 128 + c4;
    const float dg = degf(r, cc);
    const float di = rsqrtf(dg);

    float4 v = base[(size_t)node * 128];
    float ax = di * v.x, ay = di * v.y, az = di * v.z, aw = di * v.w;
    if (cc > 0) {
        const float dj = rsqrtf(degf(r, cc - 1));
        float4 w = base[(size_t)(node - 1) * 128];
        ax = fmaf(dj, w.x, ax); ay = fmaf(dj, w.y, ay); az = fmaf(dj, w.z, az); aw = fmaf(dj, w.w, aw);
    }
    if (cc < GW - 1) {
        const float dj = rsqrtf(degf(r, cc + 1));
        float4 w = base[(size_t)(node + 1) * 128];
        ax = fmaf(dj, w.x, ax); ay = fmaf(dj, w.y, ay); az = fmaf(dj, w.z, az); aw = fmaf(dj, w.w, aw);
    }
    if (r > 0) {
        const float dj = rsqrtf(degf(r - 1, cc));
        float4 w = base[(size_t)(node - GW) * 128];
        ax = fmaf(dj, w.x, ax); ay = fmaf(dj, w.y, ay); az = fmaf(dj, w.z, az); aw = fmaf(dj, w.w, aw);
    }
    if (r < GH - 1) {
        const float dj = rsqrtf(degf(r + 1, cc));
        float4 w = base[(size_t)(node + GW) * 128];
        ax = fmaf(dj, w.x, ax); ay = fmaf(dj, w.y, ay); az = fmaf(dj, w.z, az); aw = fmaf(dj, w.w, aw);
    }
    const float sc = di / dg;
    float r0, r1, r2, r3;
    uint2 hi, lo;
    hi.x = pk_hi(sc * ax, sc * ay, r0, r1);
    hi.y = pk_hi(sc * az, sc * aw, r2, r3);
    lo.x = pk(r0, r1);
    lo.y = pk(r2, r3);
    const size_t e = ((size_t)b * NNODE * CCH + (size_t)node * CCH) / 4 + c4;
    ((uint2*)oh)[e] = hi;
    ((uint2*)ol)[e] = lo;
}

// ---------------- BN1 ----------------
__global__ void bn1_kernel(const float* __restrict__ hp,
                           const float* __restrict__ g1, const float* __restrict__ beta1,
                           float* __restrict__ xg)
{
    const int c = blockIdx.x * 128 + threadIdx.x;
    float pooled[BATCH];
    float mu = 0.f;
    #pragma unroll
    for (int b = 0; b < BATCH; b++) {
        float s = 0.f;
        #pragma unroll 8
        for (int k = 0; k < 32; k++) s += hp[(size_t)(b * 32 + k) * CCH + c];
        pooled[b] = s * (1.f / (float)NNODE);
        mu += pooled[b];
    }
    mu *= (1.f / (float)BATCH);
    float var = 0.f;
    #pragma unroll
    for (int b = 0; b < BATCH; b++) { const float d = pooled[b] - mu; var = fmaf(d, d, var); }
    var *= (1.f / (float)BATCH);
    const float inv = rsqrtf(var + EPSV);
    const float ga = g1[c], be = beta1[c];
    #pragma unroll
    for (int b = 0; b < BATCH; b++)
        xg[b * CCH + c] = (pooled[b] - mu) * inv * ga + be;
}

// ---------------- BN2 scale/shift ----------------
__global__ void stats_reduce_kernel(const float* __restrict__ rs, const float* __restrict__ rq,
                                    const float* __restrict__ xg,
                                    const float* __restrict__ g2, const float* __restrict__ beta2,
                                    float* __restrict__ scale, float* __restrict__ shift)
{
    const int c = blockIdx.x * 128 + threadIdx.x;
    float S = 0.f, Q = 0.f;
    #pragma unroll
    for (int b = 0; b < BATCH; b++) {
        float sb = 0.f, qb = 0.f;
        #pragma unroll 8
        for (int k = 0; k < 32; k++) {
            const size_t idx = (size_t)(b * 32 + k) * CCH + c;
            sb += rs[idx]; qb += rq[idx];
        }
        const float xv = xg[b * CCH + c];
        S += sb + 4096.f * xv;
        Q += qb + 2.f * xv * sb + 4096.f * xv * xv;
    }
    const float mu = S * (1.f / (float)MROWS);
    float var = Q * (1.f / (float)MROWS) - mu * mu;
    var = fmaxf(var, 0.f);
    const float inv = rsqrtf(var + EPSV);
    const float sc = inv * g2[c];
    scale[c] = sc;
    shift[c] = beta2[c] - mu * sc;
}

// ---------------- final: BN2 apply + transpose ----------------
__global__ void final_kernel(const float* __restrict__ res, const float* __restrict__ xg,
                             const float* __restrict__ scale, const float* __restrict__ shift,
                             float* __restrict__ out)
{
    __shared__ float tile[32][33];
    const int b = blockIdx.z;
    const int n0 = blockIdx.x * 32;
    const int c0 = blockIdx.y * 32;
    const int tx = threadIdx.x, ty = threadIdx.y;
    #pragma unroll
    for (int k = 0; k < 4; k++) {
        const int n = n0 + ty + k * 8;
        const int c = c0 + tx;
        tile[ty + k * 8][tx] = res[((size_t)b * NNODE + n) * CCH + c] + xg[b * CCH + c];
    }
    __syncthreads();
    #pragma unroll
    for (int k = 0; k < 4; k++) {
        const int c = c0 + ty + k * 8;
        const int n = n0 + tx;
        out[((size_t)b * CCH + c) * NNODE + n] = tile[tx][ty + k * 8] * scale[c] + shift[c];
    }
}

// ---------------- launch ----------------
extern "C" void kernel_launch(void* const* d_in, const int* in_sizes, int n_in,
                              void* d_out, int out_size)
{
    const float* x = nullptr;
    const float* w[4] = {nullptr, nullptr, nullptr, nullptr};
    const float* v[7] = {nullptr, nullptr, nullptr, nullptr, nullptr, nullptr, nullptr};
    int wi = 0, vi = 0;
    for (int i = 0; i < n_in; i++) {
        const int sz = in_sizes[i];
        if (sz == MROWS * CCH) { if (!x) x = (const float*)d_in[i]; }
        else if (sz == CCH * CCH) { if (wi < 4) w[wi++] = (const float*)d_in[i]; }
        else if (sz == CCH) { if (vi < 7) v[vi++] = (const float*)d_in[i]; }
    }
    const float* b_pre = v[0]; const float* b_g1 = v[1]; const float* b_g2 = v[2];
    const float* g1 = v[3];    const float* beta1 = v[4];
    const float* g2 = v[5];    const float* beta2 = v[6];

    float *p_res, *p_t, *p_hp, *p_rs, *p_rq, *p_xg, *p_sc, *p_sh;
    __nv_bfloat16 *p_ah, *p_al, *p_wh, *p_wl;
    cudaGetSymbolAddress((void**)&p_res, g_res);
    cudaGetSymbolAddress((void**)&p_t, g_t);
    cudaGetSymbolAddress((void**)&p_ah, g_ah);
    cudaGetSymbolAddress((void**)&p_al, g_al);
    cudaGetSymbolAddress((void**)&p_wh, g_wh);
    cudaGetSymbolAddress((void**)&p_wl, g_wl);
    cudaGetSymbolAddress((void**)&p_hp, g_hp);
    cudaGetSymbolAddress((void**)&p_rs, g_rs);
    cudaGetSymbolAddress((void**)&p_rq, g_rq);
    cudaGetSymbolAddress((void**)&p_xg, g_xg);
    cudaGetSymbolAddress((void**)&p_sc, g_scale);
    cudaGetSymbolAddress((void**)&p_sh, g_shift);

    float* out = (float*)d_out;

    cudaFuncSetAttribute(gemm_mma<0>, cudaFuncAttributeMaxDynamicSharedMemorySize, (int)GEMM_SMEM);
    cudaFuncSetAttribute(gemm_mma<1>, cudaFuncAttributeMaxDynamicSharedMemorySize, (int)GEMM_SMEM);

    const int agg_blocks = (BATCH * NNODE * (CCH / 4)) / 256;
    const size_t WB = (size_t)CCH * CCH;

    convert_w_kernel<<<dim3(16, 16, 4), dim3(32, 8)>>>(w[0], w[1], w[2], w[3], p_wh, p_wl);

    // dual GEMM on fp32 x: ntile 0..7 -> residual, ntile 8..15 -> xr
    gemm_mma<1><<<dim3(16, 256), 256, GEMM_SMEM>>>(
        x, nullptr, p_wh, p_wl,
        p_res, p_t, nullptr, b_pre, p_rs, p_rq,
        /*mode0=*/1 | 8 | 16, /*mode1=*/1 | 4);

    agg_split_kernel<<<agg_blocks, 256>>>(p_t, p_ah, p_al);
    gemm_mma<0><<<dim3(8, 256), 256, GEMM_SMEM>>>(
        p_ah, p_al, p_wh + 2 * WB, p_wl + 2 * WB,
        p_t, p_t, b_g1, nullptr, nullptr, nullptr,
        /*mode0=*/1 | 2 | 4, /*mode1=*/1 | 2 | 4);
    agg_split_kernel<<<agg_blocks, 256>>>(p_t, p_ah, p_al);
    gemm_mma<0><<<dim3(8, 256), 256, GEMM_SMEM>>>(
        p_ah, p_al, p_wh + 3 * WB, p_wl + 3 * WB,
        nullptr, nullptr, b_g2, b_g2, p_hp, nullptr,
        /*mode0=*/2 | 4 | 8, /*mode1=*/2 | 4 | 8);

    bn1_kernel<<<4, 128>>>(p_hp, g1, beta1, p_xg);
    stats_reduce_kernel<<<4, 128>>>(p_rs, p_rq, p_xg, g2, beta2, p_sc, p_sh);
    final_kernel<<<dim3(NNODE / 32, CCH / 32, BATCH), dim3(32, 8)>>>(p_res, p_xg, p_sc, p_sh, out);
}

// round 9
// speedup vs baseline: 1.1674x; 1.1674x over previous
#include <cuda_runtime.h>
#include <cuda_bf16.h>
#include <cstdint>
#include <math.h>

#define BATCH 8
#define GH 64
#define GW 64
#define NNODE 4096
#define CCH 512
#define MROWS (BATCH * NNODE)
#define EPSV 1e-5f

// ---------------- scratch ----------------
__device__ float g_res[MROWS * CCH];
__device__ float g_t[MROWS * CCH];
__device__ __nv_bfloat16 g_ah[MROWS * CCH];
__device__ __nv_bfloat16 g_al[MROWS * CCH];
__device__ __nv_bfloat16 g_wh[4 * CCH * CCH];
__device__ __nv_bfloat16 g_wl[4 * CCH * CCH];
__device__ float g_hp[512 * CCH];
__device__ float g_rs[256 * CCH];
__device__ float g_rq[256 * CCH];
__device__ float g_xg[BATCH * CCH];
__device__ float g_bv[CCH];
__device__ float g_scale[CCH];
__device__ float g_shift[CCH];

// ---------------- helpers ----------------
__device__ __forceinline__ uint32_t smem_u32(const void* p) {
    uint32_t a;
    asm("{ .reg .u64 t; cvta.to.shared.u64 t, %1; cvt.u32.u64 %0, t; }" : "=r"(a) : "l"(p));
    return a;
}
__device__ __forceinline__ void ldsm_x4(uint32_t addr, uint32_t* r) {
    asm volatile("ldmatrix.sync.aligned.m8n8.x4.shared.b16 {%0,%1,%2,%3}, [%4];"
                 : "=r"(r[0]), "=r"(r[1]), "=r"(r[2]), "=r"(r[3]) : "r"(addr));
}
__device__ __forceinline__ void mma16816(float* c, const uint32_t* a, const uint32_t* b) {
    asm volatile("mma.sync.aligned.m16n8k16.row.col.f32.bf16.bf16.f32 "
                 "{%0,%1,%2,%3}, {%4,%5,%6,%7}, {%8,%9}, {%0,%1,%2,%3};"
                 : "+f"(c[0]), "+f"(c[1]), "+f"(c[2]), "+f"(c[3])
                 : "r"(a[0]), "r"(a[1]), "r"(a[2]), "r"(a[3]), "r"(b[0]), "r"(b[1]));
}
__device__ __forceinline__ void cp16(uint32_t dst, const void* src) {
    asm volatile("cp.async.cg.shared.global [%0], [%1], 16;" :: "r"(dst), "l"(src) : "memory");
}
#define CP_COMMIT() asm volatile("cp.async.commit_group;" ::: "memory")
#define CP_WAIT0()  asm volatile("cp.async.wait_group 0;" ::: "memory")
#define CP_WAIT1()  asm volatile("cp.async.wait_group 1;" ::: "memory")

__device__ __forceinline__ uint32_t pk_hi(float x, float y, float& rx, float& ry) {
    __nv_bfloat16 hx = __float2bfloat16(x), hy = __float2bfloat16(y);
    rx = x - __bfloat162float(hx);
    ry = y - __bfloat162float(hy);
    return (uint32_t)__bfloat16_as_ushort(hx) | ((uint32_t)__bfloat16_as_ushort(hy) << 16);
}
__device__ __forceinline__ uint32_t pk(float x, float y) {
    return (uint32_t)__bfloat16_as_ushort(__float2bfloat16(x))
         | ((uint32_t)__bfloat16_as_ushort(__float2bfloat16(y)) << 16);
}

// ---------------- mma.sync split-bf16 GEMM, 128x128 tile, 3-stage SW128 (R7) ---
// mode bits: 1=store C, 2=relu, 4=bias, 8=column-sum partials, 16=also sumsq
#define TILE16 16384u
#define STAGEB 32768u
#define GEMM_SMEM (3u * STAGEB)

template<int AFP32>
__global__ __launch_bounds__(256, 2)
void gemm_mma(const void* __restrict__ A0, const void* __restrict__ A1,
              const __nv_bfloat16* __restrict__ Bh, const __nv_bfloat16* __restrict__ Bl,
              float* __restrict__ C0, float* __restrict__ C1,
              const float* __restrict__ bias0, const float* __restrict__ bias1,
              float* __restrict__ redS, float* __restrict__ redQ,
              int mode0, int mode1)
{
    extern __shared__ __align__(128) char smem[];
    const uint32_t sb = smem_u32(smem);
    const int tid = threadIdx.x;
    const int wid = tid >> 5;
    const int lane = tid & 31;
    const int wm = wid & 1;
    const int wn = wid >> 1;
    const int mtile = blockIdx.y;
    const int ntile = blockIdx.x;

    const __nv_bfloat16* src0 = (const __nv_bfloat16*)A0 + (size_t)mtile * 128 * 512;
    const __nv_bfloat16* src1 = (const __nv_bfloat16*)A1 + (size_t)mtile * 128 * 512;
    const float* srcx = (const float*)A0 + (size_t)mtile * 128 * 512;
    const __nv_bfloat16* src2 = Bh + (size_t)ntile * 128 * 512;
    const __nv_bfloat16* src3 = Bl + (size_t)ntile * 128 * 512;

    float acc[4][4][4];
    #pragma unroll
    for (int i = 0; i < 4; i++)
        #pragma unroll
        for (int j = 0; j < 4; j++)
            #pragma unroll
            for (int k = 0; k < 4; k++) acc[i][j][k] = 0.f;

    const int lr = lane & 15;
    const int lk = lane >> 4;
    const int bn = (lane & 7) + ((lane >> 4) << 3);
    const int bkc2 = (lane >> 3) & 1;

    const int au_row[2] = { tid >> 2, (256 + tid) >> 2 };
    const int au_ch = tid & 3;
    float4 ra[2][2];

    #define LOAD_STAGE_BF16(kc, st) do { \
        const int _kc = (kc); const uint32_t _b = sb + (uint32_t)(st) * STAGEB; \
        _Pragma("unroll") \
        for (int p = 0; p < 8; p++) { \
            const int id = p * 256 + tid; \
            const int sel = id >> 10; \
            const int e = id & 1023; \
            const int row = e >> 3, j = e & 7; \
            const uint32_t dst = _b + (uint32_t)sel * TILE16 + (uint32_t)row * 128u \
                               + (uint32_t)((j ^ (row & 7)) << 4); \
            const __nv_bfloat16* s = (sel == 0 ? (j < 4 ? src0 : src1) : (j < 4 ? src2 : src3)) \
                                     + (size_t)row * 512 + (size_t)_kc * 32 + (j & 3) * 8; \
            cp16(dst, s); \
        } \
        CP_COMMIT(); \
    } while (0)

    #define LOAD_STAGE_B(kc, st) do { \
        const int _kc = (kc); const uint32_t _b = sb + (uint32_t)(st) * STAGEB + TILE16; \
        _Pragma("unroll") \
        for (int p = 0; p < 4; p++) { \
            const int id = p * 256 + tid; \
            const int row = id >> 3, j = id & 7; \
            const uint32_t dst = _b + (uint32_t)row * 128u + (uint32_t)((j ^ (row & 7)) << 4); \
            const __nv_bfloat16* s = (j < 4 ? src2 : src3) \
                                     + (size_t)row * 512 + (size_t)_kc * 32 + (j & 3) * 8; \
            cp16(dst, s); \
        } \
        CP_COMMIT(); \
    } while (0)

    #define LOAD_A_F32(kc) do { \
        const int _kc = (kc); \
        _Pragma("unroll") \
        for (int i = 0; i < 2; i++) { \
            const float* s = srcx + (size_t)au_row[i] * 512 + (size_t)_kc * 32 + au_ch * 8; \
            ra[i][0] = *(const float4*)s; \
            ra[i][1] = *(const float4*)(s + 4); \
        } \
    } while (0)

    #define STORE_A_F32(st) do { \
        const uint32_t _o = (uint32_t)(st) * STAGEB; \
        _Pragma("unroll") \
        for (int i = 0; i < 2; i++) { \
            float r0, r1, r2, r3, r4, r5, r6, r7; \
            uint4 hi, lo; \
            hi.x = pk_hi(ra[i][0].x, ra[i][0].y, r0, r1); \
            hi.y = pk_hi(ra[i][0].z, ra[i][0].w, r2, r3); \
            hi.z = pk_hi(ra[i][1].x, ra[i][1].y, r4, r5); \
            hi.w = pk_hi(ra[i][1].z, ra[i][1].w, r6, r7); \
            lo.x = pk(r0, r1); lo.y = pk(r2, r3); lo.z = pk(r4, r5); lo.w = pk(r6, r7); \
            const int sw = au_row[i] & 7; \
            *(uint4*)(smem + _o + (uint32_t)au_row[i] * 128u + (uint32_t)((au_ch ^ sw) << 4)) = hi; \
            *(uint4*)(smem + _o + (uint32_t)au_row[i] * 128u + (uint32_t)(((au_ch + 4) ^ sw) << 4)) = lo; \
        } \
    } while (0)

    if (AFP32) {
        LOAD_A_F32(0); STORE_A_F32(0);
        LOAD_STAGE_B(0, 0);
        LOAD_STAGE_B(1, 1);
    } else {
        LOAD_STAGE_BF16(0, 0);
        LOAD_STAGE_BF16(1, 1);
    }

    #pragma unroll 1
    for (int kc = 0; kc < 16; kc++) {
        if (kc < 15) { CP_WAIT1(); } else { CP_WAIT0(); }
        __syncthreads();
        const int st = kc % 3;
        if (kc + 2 < 16) {
            const int st2 = (kc + 2) % 3;
            if (AFP32) LOAD_STAGE_B(kc + 2, st2);
            else       LOAD_STAGE_BF16(kc + 2, st2);
        }
        if (AFP32 && kc + 1 < 16) LOAD_A_F32(kc + 1);

        const uint32_t baseA = sb + (uint32_t)st * STAGEB;
        const uint32_t baseB = baseA + TILE16;
        #pragma unroll
        for (int ks = 0; ks < 2; ks++) {
            uint32_t ah[4][4], al[4][4];
            #pragma unroll
            for (int mi = 0; mi < 4; mi++) {
                const int R = wm * 64 + mi * 16 + lr;
                const int sw = R & 7;
                const int ch = 2 * ks + lk;
                ldsm_x4(baseA + (uint32_t)R * 128u + (uint32_t)((ch ^ sw) << 4), ah[mi]);
                ldsm_x4(baseA + (uint32_t)R * 128u + (uint32_t)(((ch + 4) ^ sw) << 4), al[mi]);
            }
            #pragma unroll
            for (int np = 0; np < 2; np++) {
                uint32_t bh[2][2], bl[2][2];
                const int R = wn * 32 + np * 16 + bn;
                const int sw = R & 7;
                const int ch = 2 * ks + bkc2;
                uint32_t r[4];
                ldsm_x4(baseB + (uint32_t)R * 128u + (uint32_t)((ch ^ sw) << 4), r);
                bh[0][0] = r[0]; bh[0][1] = r[1]; bh[1][0] = r[2]; bh[1][1] = r[3];
                ldsm_x4(baseB + (uint32_t)R * 128u + (uint32_t)(((ch + 4) ^ sw) << 4), r);
                bl[0][0] = r[0]; bl[0][1] = r[1]; bl[1][0] = r[2]; bl[1][1] = r[3];
                #pragma unroll
                for (int mi = 0; mi < 4; mi++)
                    #pragma unroll
                    for (int b2 = 0; b2 < 2; b2++) {
                        const int nb = np * 2 + b2;
                        mma16816(acc[mi][nb], ah[mi], bh[b2]);
                        mma16816(acc[mi][nb], ah[mi], bl[b2]);
                        mma16816(acc[mi][nb], al[mi], bh[b2]);
                    }
            }
        }
        if (AFP32 && kc + 1 < 16) STORE_A_F32((kc + 1) % 3);
    }

    // ---------------- epilogue ----------------
    const int selc = ntile >> 2;
    const int mode = selc ? mode1 : mode0;
    const float* bias = selc ? bias1 : bias0;
    float* C = selc ? C1 : C0;
    const int ncol = (ntile & 3) * 128;

    const int gid = lane >> 2;
    const int tig = lane & 3;

    float rsum[4][2], rq[4][2];
    #pragma unroll
    for (int nb = 0; nb < 4; nb++) { rsum[nb][0] = rsum[nb][1] = rq[nb][0] = rq[nb][1] = 0.f; }

    #pragma unroll
    for (int mi = 0; mi < 4; mi++) {
        const int row0 = mtile * 128 + wm * 64 + mi * 16 + gid;
        #pragma unroll
        for (int nb = 0; nb < 4; nb++) {
            const int col = ncol + wn * 32 + nb * 8 + tig * 2;
            float b0 = 0.f, b1 = 0.f;
            if (mode & 4) { b0 = __ldg(bias + col); b1 = __ldg(bias + col + 1); }
            float v0 = acc[mi][nb][0] + b0, v1 = acc[mi][nb][1] + b1;
            float v2 = acc[mi][nb][2] + b0, v3 = acc[mi][nb][3] + b1;
            if (mode & 2) {
                v0 = fmaxf(v0, 0.f); v1 = fmaxf(v1, 0.f);
                v2 = fmaxf(v2, 0.f); v3 = fmaxf(v3, 0.f);
            }
            if (mode & 1) {
                *(float2*)(C + (size_t)row0 * 512 + col) = make_float2(v0, v1);
                *(float2*)(C + (size_t)(row0 + 8) * 512 + col) = make_float2(v2, v3);
            }
            if (mode & 8) {
                rsum[nb][0] += v0 + v2; rsum[nb][1] += v1 + v3;
                if (mode & 16) {
                    rq[nb][0] = fmaf(v0, v0, fmaf(v2, v2, rq[nb][0]));
                    rq[nb][1] = fmaf(v1, v1, fmaf(v3, v3, rq[nb][1]));
                }
            }
        }
    }

    if (mode & 8) {
        #pragma unroll
        for (int nb = 0; nb < 4; nb++)
            #pragma unroll
            for (int j = 0; j < 2; j++) {
                #pragma unroll
                for (int m = 4; m <= 16; m <<= 1) {
                    rsum[nb][j] += __shfl_xor_sync(0xffffffffu, rsum[nb][j], m);
                    rq[nb][j]   += __shfl_xor_sync(0xffffffffu, rq[nb][j], m);
                }
            }
        __syncthreads();
        float* red = (float*)smem;
        if (gid == 0) {
            #pragma unroll
            for (int nb = 0; nb < 4; nb++) {
                const int c = wn * 32 + nb * 8 + tig * 2;
                red[wm * 128 + c]     = rsum[nb][0];
                red[wm * 128 + c + 1] = rsum[nb][1];
                red[256 + wm * 128 + c]     = rq[nb][0];
                red[256 + wm * 128 + c + 1] = rq[nb][1];
            }
        }
        __syncthreads();
        if (tid < 128) {
            const float s = red[tid] + red[128 + tid];
            redS[(size_t)mtile * 512 + ncol + tid] = s;
            if (mode & 16) {
                const float q = red[256 + tid] + red[384 + tid];
                redQ[(size_t)mtile * 512 + ncol + tid] = q;
            }
        }
    }
}

// ---------------- convert+transpose weights (w_res -> blk0, w_g2 -> blk3) ------
__global__ void convert_w_kernel(const float* __restrict__ w0, const float* __restrict__ w3,
                                 __nv_bfloat16* __restrict__ wh, __nv_bfloat16* __restrict__ wl)
{
    __shared__ float t[32][33];
    const int wsel = blockIdx.z;           // 0 or 1
    const float* w = wsel == 0 ? w0 : w3;
    const size_t off = (size_t)(wsel == 0 ? 0 : 3) * CCH * CCH;
    __nv_bfloat16* oh = wh + off;
    __nv_bfloat16* ol = wl + off;
    const int n0 = blockIdx.x * 32;
    const int k0 = blockIdx.y * 32;
    const int tx = threadIdx.x, ty = threadIdx.y;
    #pragma unroll
    for (int j = 0; j < 4; j++)
        t[ty + j * 8][tx] = w[(size_t)(k0 + ty + j * 8) * 512 + n0 + tx];
    __syncthreads();
    #pragma unroll
    for (int j = 0; j < 4; j++) {
        const float v = t[tx][ty + j * 8];
        const __nv_bfloat16 hb = __float2bfloat16(v);
        oh[(size_t)(n0 + ty + j * 8) * 512 + k0 + tx] = hb;
        ol[(size_t)(n0 + ty + j * 8) * 512 + k0 + tx] = __float2bfloat16(v - __bfloat162float(hb));
    }
}

// ---------------- Wc = w_pre @ w_g1 (fp32), stored transposed split -> blk1 ----
__global__ void wc_kernel(const float* __restrict__ wpre, const float* __restrict__ wg1,
                          __nv_bfloat16* __restrict__ wh, __nv_bfloat16* __restrict__ wl)
{
    __shared__ float sA[32][33];  // [k][j]
    __shared__ float sB[32][33];  // [j][n]
    const int n0 = blockIdx.x * 32, k0 = blockIdx.y * 32;
    const int tx = threadIdx.x, ty = threadIdx.y;  // (32,8)
    float acc[4] = {0.f, 0.f, 0.f, 0.f};
    for (int j0 = 0; j0 < 512; j0 += 32) {
        #pragma unroll
        for (int q = 0; q < 4; q++) {
            sA[ty + 8 * q][tx] = wpre[(size_t)(k0 + ty + 8 * q) * 512 + j0 + tx];
            sB[ty + 8 * q][tx] = wg1[(size_t)(j0 + ty + 8 * q) * 512 + n0 + tx];
        }
        __syncthreads();
        #pragma unroll
        for (int jj = 0; jj < 32; jj++) {
            const float b = sB[jj][tx];
            #pragma unroll
            for (int q = 0; q < 4; q++) acc[q] = fmaf(sA[ty + 8 * q][jj], b, acc[q]);
        }
        __syncthreads();
    }
    __nv_bfloat16* oh = wh + (size_t)1 * CCH * CCH;
    __nv_bfloat16* ol = wl + (size_t)1 * CCH * CCH;
    #pragma unroll
    for (int q = 0; q < 4; q++) {
        const int k = k0 + ty + 8 * q, n = n0 + tx;
        const __nv_bfloat16 hb = __float2bfloat16(acc[q]);
        oh[(size_t)n * 512 + k] = hb;
        ol[(size_t)n * 512 + k] = __float2bfloat16(acc[q] - __bfloat162float(hb));
    }
}

// ---------------- bv = b_pre @ w_g1 ----------------
__global__ void bv_kernel(const float* __restrict__ bpre, const float* __restrict__ wg1,
                          float* __restrict__ bv)
{
    const int n = blockIdx.x * 256 + threadIdx.x;
    float s = 0.f;
    for (int j = 0; j < 512; j++) s = fmaf(bpre[j], wg1[(size_t)j * 512 + n], s);
    bv[n] = s;
}

// ---------------- GCN geometry ----------------
__device__ __forceinline__ float degf(int r, int c) {
    return 1.f + (float)(c > 0) + (float)(c < GW - 1) + (float)(r > 0) + (float)(r < GH - 1);
}
__device__ __forceinline__ float dinvf(float dg) {
    return dg == 3.f ? 0.57735026918962576f : (dg == 4.f ? 0.5f : 0.44721359549995794f);
}

// ---------------- agg_h1: h1 = relu(Agg(z0) + s_i*bv + b_g1), split bf16 -------
__global__ void agg_h1_kernel(const float* __restrict__ in,
                              const float* __restrict__ bv, const float* __restrict__ bg1,
                              __nv_bfloat16* __restrict__ oh, __nv_bfloat16* __restrict__ ol)
{
    const int idx = blockIdx.x * 256 + threadIdx.x;
    const int c4 = idx & 127;
    const int node = (idx >> 7) & (NNODE - 1);
    const int b = idx >> 19;
    const int r = node >> 6;
    const int cc = node & 63;

    const float4* base = (const float4*)in + (size_t)b * NNODE * 128 + c4;
    const float dg = degf(r, cc);
    const float di = dinvf(dg);

    float4 v = base[(size_t)node * 128];
    float ax = di * v.x, ay = di * v.y, az = di * v.z, aw = di * v.w;
    float sumdj = di;
    if (cc > 0) {
        const float dj = dinvf(degf(r, cc - 1)); sumdj += dj;
        float4 w = base[(size_t)(node - 1) * 128];
        ax = fmaf(dj, w.x, ax); ay = fmaf(dj, w.y, ay); az = fmaf(dj, w.z, az); aw = fmaf(dj, w.w, aw);
    }
    if (cc < GW - 1) {
        const float dj = dinvf(degf(r, cc + 1)); sumdj += dj;
        float4 w = base[(size_t)(node + 1) * 128];
        ax = fmaf(dj, w.x, ax); ay = fmaf(dj, w.y, ay); az = fmaf(dj, w.z, az); aw = fmaf(dj, w.w, aw);
    }
    if (r > 0) {
        const float dj = dinvf(degf(r - 1, cc)); sumdj += dj;
        float4 w = base[(size_t)(node - GW) * 128];
        ax = fmaf(dj, w.x, ax); ay = fmaf(dj, w.y, ay); az = fmaf(dj, w.z, az); aw = fmaf(dj, w.w, aw);
    }
    if (r < GH - 1) {
        const float dj = dinvf(degf(r + 1, cc)); sumdj += dj;
        float4 w = base[(size_t)(node + GW) * 128];
        ax = fmaf(dj, w.x, ax); ay = fmaf(dj, w.y, ay); az = fmaf(dj, w.z, az); aw = fmaf(dj, w.w, aw);
    }
    const float sc = di / dg;
    const float sn = sc * sumdj;
    const float4 bvv = *(const float4*)(bv + c4 * 4);
    const float4 bgv = *(const float4*)(bg1 + c4 * 4);
    float o0 = fmaxf(fmaf(sc, ax, fmaf(sn, bvv.x, bgv.x)), 0.f);
    float o1 = fmaxf(fmaf(sc, ay, fmaf(sn, bvv.y, bgv.y)), 0.f);
    float o2 = fmaxf(fmaf(sc, az, fmaf(sn, bvv.z, bgv.z)), 0.f);
    float o3 = fmaxf(fmaf(sc, aw, fmaf(sn, bvv.w, bgv.w)), 0.f);
    float r0, r1, r2, r3;
    uint2 hi, lo;
    hi.x = pk_hi(o0, o1, r0, r1);
    hi.y = pk_hi(o2, o3, r2, r3);
    lo.x = pk(r0, r1);
    lo.y = pk(r2, r3);
    const size_t e = ((size_t)b * NNODE * CCH + (size_t)node * CCH) / 4 + c4;
    ((uint2*)oh)[e] = hi;
    ((uint2*)ol)[e] = lo;
}

// ---------------- agg_h2: hp partials of relu(Agg(y) + b_g2), no h2 store ------
// block = (batch b, grid row r); 256 threads, each owns channels tid and tid+256.
__global__ void agg_h2_kernel(const float* __restrict__ y, const float* __restrict__ bg2,
                              float* __restrict__ hp)
{
    const int blk = blockIdx.x;   // 0..511
    const int b = blk >> 6;
    const int r = blk & 63;
    const int tid = threadIdx.x;
    const float* yb = y + (size_t)b * NNODE * CCH;
    const float bgA = bg2[tid], bgB = bg2[tid + 256];
    float a0 = 0.f, a1 = 0.f;
    const int rbase = r * 64;
    #pragma unroll 2
    for (int cc = 0; cc < 64; cc++) {
        const int node = rbase + cc;
        const float dg = degf(r, cc);
        const float di = dinvf(dg);
        const float sc = di / dg;
        const float* p = yb + (size_t)node * 512 + tid;
        float s0 = di * p[0];
        float s1 = di * p[256];
        if (cc > 0) {
            const float dj = dinvf(degf(r, cc - 1));
            s0 = fmaf(dj, p[-512], s0); s1 = fmaf(dj, p[-512 + 256], s1);
        }
        if (cc < 63) {
            const float dj = dinvf(degf(r, cc + 1));
            s0 = fmaf(dj, p[512], s0); s1 = fmaf(dj, p[512 + 256], s1);
        }
        if (r > 0) {
            const float dj = dinvf(degf(r - 1, cc));
            s0 = fmaf(dj, p[-64 * 512], s0); s1 = fmaf(dj, p[-64 * 512 + 256], s1);
        }
        if (r < 63) {
            const float dj = dinvf(degf(r + 1, cc));
            s0 = fmaf(dj, p[64 * 512], s0); s1 = fmaf(dj, p[64 * 512 + 256], s1);
        }
        a0 += fmaxf(fmaf(sc, s0, bgA), 0.f);
        a1 += fmaxf(fmaf(sc, s1, bgB), 0.f);
    }
    hp[(size_t)blk * 512 + tid] = a0;
    hp[(size_t)blk * 512 + tid + 256] = a1;
}

// ---------------- BN1 from hp (512 partial rows) ----------------
__global__ void bn1_kernel(const float* __restrict__ hp,
                           const float* __restrict__ g1, const float* __restrict__ beta1,
                           float* __restrict__ xg)
{
    const int c = blockIdx.x * 128 + threadIdx.x;
    float pooled[BATCH];
    float mu = 0.f;
    #pragma unroll
    for (int b = 0; b < BATCH; b++) {
        float s = 0.f;
        #pragma unroll 8
        for (int k = 0; k < 64; k++) s += hp[(size_t)(b * 64 + k) * CCH + c];
        pooled[b] = s * (1.f / (float)NNODE);
        mu += pooled[b];
    }
    mu *= (1.f / (float)BATCH);
    float var = 0.f;
    #pragma unroll
    for (int b = 0; b < BATCH; b++) { const float d = pooled[b] - mu; var = fmaf(d, d, var); }
    var *= (1.f / (float)BATCH);
    const float inv = rsqrtf(var + EPSV);
    const float ga = g1[c], be = beta1[c];
    #pragma unroll
    for (int b = 0; b < BATCH; b++)
        xg[b * CCH + c] = (pooled[b] - mu) * inv * ga + be;
}

// ---------------- BN2 scale/shift ----------------
__global__ void stats_reduce_kernel(const float* __restrict__ rs, const float* __restrict__ rq,
                                    const float* __restrict__ xg,
                                    const float* __restrict__ g2, const float* __restrict__ beta2,
                                    float* __restrict__ scale, float* __restrict__ shift)
{
    const int c = blockIdx.x * 128 + threadIdx.x;
    float S = 0.f, Q = 0.f;
    #pragma unroll
    for (int b = 0; b < BATCH; b++) {
        float sb = 0.f, qb = 0.f;
        #pragma unroll 8
        for (int k = 0; k < 32; k++) {
            const size_t idx = (size_t)(b * 32 + k) * CCH + c;
            sb += rs[idx]; qb += rq[idx];
        }
        const float xv = xg[b * CCH + c];
        S += sb + 4096.f * xv;
        Q += qb + 2.f * xv * sb + 4096.f * xv * xv;
    }
    const float mu = S * (1.f / (float)MROWS);
    float var = Q * (1.f / (float)MROWS) - mu * mu;
    var = fmaxf(var, 0.f);
    const float inv = rsqrtf(var + EPSV);
    const float sc = inv * g2[c];
    scale[c] = sc;
    shift[c] = beta2[c] - mu * sc;
}

// ---------------- final: BN2 apply + transpose ----------------
__global__ void final_kernel(const float* __restrict__ res, const float* __restrict__ xg,
                             const float* __restrict__ scale, const float* __restrict__ shift,
                             float* __restrict__ out)
{
    __shared__ float tile[32][33];
    const int b = blockIdx.z;
    const int n0 = blockIdx.x * 32;
    const int c0 = blockIdx.y * 32;
    const int tx = threadIdx.x, ty = threadIdx.y;
    #pragma unroll
    for (int k = 0; k < 4; k++) {
        const int n = n0 + ty + k * 8;
        const int c = c0 + tx;
        tile[ty + k * 8][tx] = res[((size_t)b * NNODE + n) * CCH + c] + xg[b * CCH + c];
    }
    __syncthreads();
    #pragma unroll
    for (int k = 0; k < 4; k++) {
        const int c = c0 + ty + k * 8;
        const int n = n0 + tx;
        out[((size_t)b * CCH + c) * NNODE + n] = tile[tx][ty + k * 8] * scale[c] + shift[c];
    }
}

// ---------------- launch ----------------
extern "C" void kernel_launch(void* const* d_in, const int* in_sizes, int n_in,
                              void* d_out, int out_size)
{
    const float* x = nullptr;
    const float* w[4] = {nullptr, nullptr, nullptr, nullptr};
    const float* v[7] = {nullptr, nullptr, nullptr, nullptr, nullptr, nullptr, nullptr};
    int wi = 0, vi = 0;
    for (int i = 0; i < n_in; i++) {
        const int sz = in_sizes[i];
        if (sz == MROWS * CCH) { if (!x) x = (const float*)d_in[i]; }
        else if (sz == CCH * CCH) { if (wi < 4) w[wi++] = (const float*)d_in[i]; }
        else if (sz == CCH) { if (vi < 7) v[vi++] = (const float*)d_in[i]; }
    }
    const float* b_pre = v[0]; const float* b_g1 = v[1]; const float* b_g2 = v[2];
    const float* g1 = v[3];    const float* beta1 = v[4];
    const float* g2 = v[5];    const float* beta2 = v[6];

    float *p_res, *p_t, *p_hp, *p_rs, *p_rq, *p_xg, *p_bv, *p_sc, *p_sh;
    __nv_bfloat16 *p_ah, *p_al, *p_wh, *p_wl;
    cudaGetSymbolAddress((void**)&p_res, g_res);
    cudaGetSymbolAddress((void**)&p_t, g_t);
    cudaGetSymbolAddress((void**)&p_ah, g_ah);
    cudaGetSymbolAddress((void**)&p_al, g_al);
    cudaGetSymbolAddress((void**)&p_wh, g_wh);
    cudaGetSymbolAddress((void**)&p_wl, g_wl);
    cudaGetSymbolAddress((void**)&p_hp, g_hp);
    cudaGetSymbolAddress((void**)&p_rs, g_rs);
    cudaGetSymbolAddress((void**)&p_rq, g_rq);
    cudaGetSymbolAddress((void**)&p_xg, g_xg);
    cudaGetSymbolAddress((void**)&p_bv, g_bv);
    cudaGetSymbolAddress((void**)&p_sc, g_scale);
    cudaGetSymbolAddress((void**)&p_sh, g_shift);

    float* out = (float*)d_out;

    cudaFuncSetAttribute(gemm_mma<0>, cudaFuncAttributeMaxDynamicSharedMemorySize, (int)GEMM_SMEM);
    cudaFuncSetAttribute(gemm_mma<1>, cudaFuncAttributeMaxDynamicSharedMemorySize, (int)GEMM_SMEM);

    const int agg_blocks = (BATCH * NNODE * (CCH / 4)) / 256;
    const size_t WB = (size_t)CCH * CCH;

    // weight prep: w_res -> blk0, w_g2 -> blk3, Wc = w_pre@w_g1 -> blk1, bv
    convert_w_kernel<<<dim3(16, 16, 2), dim3(32, 8)>>>(w[0], w[3], p_wh, p_wl);
    wc_kernel<<<dim3(16, 16), dim3(32, 8)>>>(w[1], w[2], p_wh, p_wl);
    bv_kernel<<<2, 256>>>(b_pre, w[2], p_bv);

    // dual GEMM on fp32 x: ntile 0..3 -> residual (store + stats partials),
    //                      ntile 4..7 -> z0 = x @ Wc (plain store)
    gemm_mma<1><<<dim3(8, 256), 256, GEMM_SMEM>>>(
        x, nullptr, p_wh, p_wl,
        p_res, p_t, nullptr, nullptr, p_rs, p_rq,
        /*mode0=*/1 | 8 | 16, /*mode1=*/1);

    // h1 = relu(Agg(z0) + s*bv + b_g1) -> split bf16
    agg_h1_kernel<<<agg_blocks, 256>>>(p_t, p_bv, b_g1, p_ah, p_al);

    // y = h1 @ w_g2 (plain store)
    gemm_mma<0><<<dim3(4, 256), 256, GEMM_SMEM>>>(
        p_ah, p_al, p_wh + 3 * WB, p_wl + 3 * WB,
        p_t, p_t, nullptr, nullptr, nullptr, nullptr,
        /*mode0=*/1, /*mode1=*/0);

    // pooled partials of h2 = relu(Agg(y) + b_g2), no h2 materialization
    agg_h2_kernel<<<512, 256>>>(p_t, b_g2, p_hp);

    bn1_kernel<<<4, 128>>>(p_hp, g1, beta1, p_xg);
    stats_reduce_kernel<<<4, 128>>>(p_rs, p_rq, p_xg, g2, beta2, p_sc, p_sh);
    final_kernel<<<dim3(NNODE / 32, CCH / 32, BATCH), dim3(32, 8)>>>(p_res, p_xg, p_sc, p_sh, out);
}

// round 10
// speedup vs baseline: 1.2539x; 1.0741x over previous
#include <cuda_runtime.h>
#include <cuda_bf16.h>
#include <cstdint>
#include <math.h>

#define BATCH 8
#define GH 64
#define GW 64
#define NNODE 4096
#define CCH 512
#define MROWS (BATCH * NNODE)
#define EPSV 1e-5f

// ---------------- scratch ----------------
__device__ float g_res[MROWS * CCH];
__device__ __nv_bfloat16 g_xah[MROWS * CCH];  // Agg(x) hi
__device__ __nv_bfloat16 g_xal[MROWS * CCH];  // Agg(x) lo
__device__ __nv_bfloat16 g_h1h[MROWS * CCH];  // h1 hi
__device__ __nv_bfloat16 g_h1l[MROWS * CCH];  // h1 lo
__device__ __nv_bfloat16 g_yh[MROWS * CCH];   // Agg(h1) hi
__device__ __nv_bfloat16 g_yl[MROWS * CCH];   // Agg(h1) lo
__device__ __nv_bfloat16 g_wh[4 * CCH * CCH];
__device__ __nv_bfloat16 g_wl[4 * CCH * CCH];
__device__ float g_hp[256 * CCH];
__device__ float g_rs[256 * CCH];
__device__ float g_rq[256 * CCH];
__device__ float g_xg[BATCH * CCH];
__device__ float g_bv[CCH];
__device__ float g_scale[CCH];
__device__ float g_shift[CCH];

// ---------------- helpers ----------------
__device__ __forceinline__ uint32_t smem_u32(const void* p) {
    uint32_t a;
    asm("{ .reg .u64 t; cvta.to.shared.u64 t, %1; cvt.u32.u64 %0, t; }" : "=r"(a) : "l"(p));
    return a;
}
__device__ __forceinline__ void ldsm_x4(uint32_t addr, uint32_t* r) {
    asm volatile("ldmatrix.sync.aligned.m8n8.x4.shared.b16 {%0,%1,%2,%3}, [%4];"
                 : "=r"(r[0]), "=r"(r[1]), "=r"(r[2]), "=r"(r[3]) : "r"(addr));
}
__device__ __forceinline__ void mma16816(float* c, const uint32_t* a, const uint32_t* b) {
    asm volatile("mma.sync.aligned.m16n8k16.row.col.f32.bf16.bf16.f32 "
                 "{%0,%1,%2,%3}, {%4,%5,%6,%7}, {%8,%9}, {%0,%1,%2,%3};"
                 : "+f"(c[0]), "+f"(c[1]), "+f"(c[2]), "+f"(c[3])
                 : "r"(a[0]), "r"(a[1]), "r"(a[2]), "r"(a[3]), "r"(b[0]), "r"(b[1]));
}
__device__ __forceinline__ void cp16(uint32_t dst, const void* src) {
    asm volatile("cp.async.cg.shared.global [%0], [%1], 16;" :: "r"(dst), "l"(src) : "memory");
}
#define CP_COMMIT() asm volatile("cp.async.commit_group;" ::: "memory")
#define CP_WAIT0()  asm volatile("cp.async.wait_group 0;" ::: "memory")
#define CP_WAIT1()  asm volatile("cp.async.wait_group 1;" ::: "memory")

__device__ __forceinline__ uint32_t pk_hi(float x, float y, float& rx, float& ry) {
    __nv_bfloat16 hx = __float2bfloat16(x), hy = __float2bfloat16(y);
    rx = x - __bfloat162float(hx);
    ry = y - __bfloat162float(hy);
    return (uint32_t)__bfloat16_as_ushort(hx) | ((uint32_t)__bfloat16_as_ushort(hy) << 16);
}
__device__ __forceinline__ uint32_t pk(float x, float y) {
    return (uint32_t)__bfloat16_as_ushort(__float2bfloat16(x))
         | ((uint32_t)__bfloat16_as_ushort(__float2bfloat16(y)) << 16);
}
__device__ __forceinline__ void unpk2(uint32_t h, uint32_t l, float& a, float& b) {
    a = __bfloat162float(__ushort_as_bfloat16((unsigned short)(h & 0xffff)))
      + __bfloat162float(__ushort_as_bfloat16((unsigned short)(l & 0xffff)));
    b = __bfloat162float(__ushort_as_bfloat16((unsigned short)(h >> 16)))
      + __bfloat162float(__ushort_as_bfloat16((unsigned short)(l >> 16)));
}

// ---------------- GCN geometry ----------------
__device__ __forceinline__ float degf(int r, int c) {
    return 1.f + (float)(c > 0) + (float)(c < GW - 1) + (float)(r > 0) + (float)(r < GH - 1);
}
__device__ __forceinline__ float dinvf(float dg) {
    return dg == 3.f ? 0.57735026918962576f : (dg == 4.f ? 0.5f : 0.44721359549995794f);
}
__device__ __forceinline__ float s_of(int node) {
    const int r = node >> 6, c = node & 63;
    const float dg = degf(r, c);
    const float di = dinvf(dg);
    float sum = di;
    if (c > 0)      sum += dinvf(degf(r, c - 1));
    if (c < GW - 1) sum += dinvf(degf(r, c + 1));
    if (r > 0)      sum += dinvf(degf(r - 1, c));
    if (r < GH - 1) sum += dinvf(degf(r + 1, c));
    return di / dg * sum;
}

// ---------------- mma.sync split-bf16 GEMM, 128x128 tile, 3-stage SW128 --------
// mode bits: 1=store C(fp32), 2=relu, 4=bias0, 8=colsum partials, 16=also sumsq,
//            32=h1 epilogue (relu(acc + s_row*bv + bg1) -> split-bf16 Hh/Hl)
#define TILE16 16384u
#define STAGEB 32768u
#define GEMM_SMEM (3u * STAGEB)

template<int AFP32>
__global__ __launch_bounds__(256, 2)
void gemm_mma(const float* __restrict__ Ax,
              const __nv_bfloat16* __restrict__ Ah, const __nv_bfloat16* __restrict__ Al,
              const __nv_bfloat16* __restrict__ Bh, const __nv_bfloat16* __restrict__ Bl,
              float* __restrict__ C0, const float* __restrict__ bias0,
              float* __restrict__ redS, float* __restrict__ redQ,
              __nv_bfloat16* __restrict__ Hh, __nv_bfloat16* __restrict__ Hl,
              const float* __restrict__ bv, const float* __restrict__ bg1,
              int mode0, int mode1)
{
    extern __shared__ __align__(128) char smem[];
    const uint32_t sb = smem_u32(smem);
    const int tid = threadIdx.x;
    const int wid = tid >> 5;
    const int lane = tid & 31;
    const int wm = wid & 1;
    const int wn = wid >> 1;
    const int mtile = blockIdx.y;
    const int ntile = blockIdx.x;
    const bool f32p = AFP32 && (ntile < 4);

    const __nv_bfloat16* src0 = Ah + (size_t)mtile * 128 * 512;
    const __nv_bfloat16* src1 = Al + (size_t)mtile * 128 * 512;
    const float* srcx = Ax + (size_t)mtile * 128 * 512;
    const __nv_bfloat16* src2 = Bh + (size_t)ntile * 128 * 512;
    const __nv_bfloat16* src3 = Bl + (size_t)ntile * 128 * 512;

    float acc[4][4][4];
    #pragma unroll
    for (int i = 0; i < 4; i++)
        #pragma unroll
        for (int j = 0; j < 4; j++)
            #pragma unroll
            for (int k = 0; k < 4; k++) acc[i][j][k] = 0.f;

    const int lr = lane & 15;
    const int lk = lane >> 4;
    const int bn = (lane & 7) + ((lane >> 4) << 3);
    const int bkc2 = (lane >> 3) & 1;

    const int au_row[2] = { tid >> 2, (256 + tid) >> 2 };
    const int au_ch = tid & 3;
    float4 ra[2][2];

    #define LOAD_STAGE_BF16(kc, st) do { \
        const int _kc = (kc); const uint32_t _b = sb + (uint32_t)(st) * STAGEB; \
        _Pragma("unroll") \
        for (int p = 0; p < 8; p++) { \
            const int id = p * 256 + tid; \
            const int sel = id >> 10; \
            const int e = id & 1023; \
            const int row = e >> 3, j = e & 7; \
            const uint32_t dst = _b + (uint32_t)sel * TILE16 + (uint32_t)row * 128u \
                               + (uint32_t)((j ^ (row & 7)) << 4); \
            const __nv_bfloat16* s = (sel == 0 ? (j < 4 ? src0 : src1) : (j < 4 ? src2 : src3)) \
                                     + (size_t)row * 512 + (size_t)_kc * 32 + (j & 3) * 8; \
            cp16(dst, s); \
        } \
        CP_COMMIT(); \
    } while (0)

    #define LOAD_STAGE_B(kc, st) do { \
        const int _kc = (kc); const uint32_t _b = sb + (uint32_t)(st) * STAGEB + TILE16; \
        _Pragma("unroll") \
        for (int p = 0; p < 4; p++) { \
            const int id = p * 256 + tid; \
            const int row = id >> 3, j = id & 7; \
            const uint32_t dst = _b + (uint32_t)row * 128u + (uint32_t)((j ^ (row & 7)) << 4); \
            const __nv_bfloat16* s = (j < 4 ? src2 : src3) \
                                     + (size_t)row * 512 + (size_t)_kc * 32 + (j & 3) * 8; \
            cp16(dst, s); \
        } \
        CP_COMMIT(); \
    } while (0)

    #define LOAD_A_F32(kc) do { \
        const int _kc = (kc); \
        _Pragma("unroll") \
        for (int i = 0; i < 2; i++) { \
            const float* s = srcx + (size_t)au_row[i] * 512 + (size_t)_kc * 32 + au_ch * 8; \
            ra[i][0] = *(const float4*)s; \
            ra[i][1] = *(const float4*)(s + 4); \
        } \
    } while (0)

    #define STORE_A_F32(st) do { \
        const uint32_t _o = (uint32_t)(st) * STAGEB; \
        _Pragma("unroll") \
        for (int i = 0; i < 2; i++) { \
            float r0, r1, r2, r3, r4, r5, r6, r7; \
            uint4 hi, lo; \
            hi.x = pk_hi(ra[i][0].x, ra[i][0].y, r0, r1); \
            hi.y = pk_hi(ra[i][0].z, ra[i][0].w, r2, r3); \
            hi.z = pk_hi(ra[i][1].x, ra[i][1].y, r4, r5); \
            hi.w = pk_hi(ra[i][1].z, ra[i][1].w, r6, r7); \
            lo.x = pk(r0, r1); lo.y = pk(r2, r3); lo.z = pk(r4, r5); lo.w = pk(r6, r7); \
            const int sw = au_row[i] & 7; \
            *(uint4*)(smem + _o + (uint32_t)au_row[i] * 128u + (uint32_t)((au_ch ^ sw) << 4)) = hi; \
            *(uint4*)(smem + _o + (uint32_t)au_row[i] * 128u + (uint32_t)(((au_ch + 4) ^ sw) << 4)) = lo; \
        } \
    } while (0)

    if (f32p) {
        LOAD_A_F32(0); STORE_A_F32(0);
        LOAD_STAGE_B(0, 0);
        LOAD_STAGE_B(1, 1);
    } else {
        LOAD_STAGE_BF16(0, 0);
        LOAD_STAGE_BF16(1, 1);
    }

    #pragma unroll 1
    for (int kc = 0; kc < 16; kc++) {
        if (kc < 15) { CP_WAIT1(); } else { CP_WAIT0(); }
        __syncthreads();
        const int st = kc % 3;
        if (kc + 2 < 16) {
            const int st2 = (kc + 2) % 3;
            if (f32p) LOAD_STAGE_B(kc + 2, st2);
            else      LOAD_STAGE_BF16(kc + 2, st2);
        }
        if (f32p && kc + 1 < 16) LOAD_A_F32(kc + 1);

        const uint32_t baseA = sb + (uint32_t)st * STAGEB;
        const uint32_t baseB = baseA + TILE16;
        #pragma unroll
        for (int ks = 0; ks < 2; ks++) {
            uint32_t ah[4][4], al[4][4];
            #pragma unroll
            for (int mi = 0; mi < 4; mi++) {
                const int R = wm * 64 + mi * 16 + lr;
                const int sw = R & 7;
                const int ch = 2 * ks + lk;
                ldsm_x4(baseA + (uint32_t)R * 128u + (uint32_t)((ch ^ sw) << 4), ah[mi]);
                ldsm_x4(baseA + (uint32_t)R * 128u + (uint32_t)(((ch + 4) ^ sw) << 4), al[mi]);
            }
            #pragma unroll
            for (int np = 0; np < 2; np++) {
                uint32_t bh[2][2], bl[2][2];
                const int R = wn * 32 + np * 16 + bn;
                const int sw = R & 7;
                const int ch = 2 * ks + bkc2;
                uint32_t r[4];
                ldsm_x4(baseB + (uint32_t)R * 128u + (uint32_t)((ch ^ sw) << 4), r);
                bh[0][0] = r[0]; bh[0][1] = r[1]; bh[1][0] = r[2]; bh[1][1] = r[3];
                ldsm_x4(baseB + (uint32_t)R * 128u + (uint32_t)(((ch + 4) ^ sw) << 4), r);
                bl[0][0] = r[0]; bl[0][1] = r[1]; bl[1][0] = r[2]; bl[1][1] = r[3];
                #pragma unroll
                for (int mi = 0; mi < 4; mi++)
                    #pragma unroll
                    for (int b2 = 0; b2 < 2; b2++) {
                        const int nb = np * 2 + b2;
                        mma16816(acc[mi][nb], ah[mi], bh[b2]);
                        mma16816(acc[mi][nb], ah[mi], bl[b2]);
                        mma16816(acc[mi][nb], al[mi], bh[b2]);
                    }
            }
        }
        if (f32p && kc + 1 < 16) STORE_A_F32((kc + 1) % 3);
    }

    // ---------------- epilogue ----------------
    const int mode = (ntile >= 4) ? mode1 : mode0;
    const int ncol = (ntile & 3) * 128;
    const int gid = lane >> 2;
    const int tig = lane & 3;

    if (mode & 32) {
        // h1 = relu(acc + s_row*bv + bg1) -> split-bf16 store
        #pragma unroll
        for (int mi = 0; mi < 4; mi++) {
            const int row0 = mtile * 128 + wm * 64 + mi * 16 + gid;
            const int rowB = row0 + 8;
            const float s0 = s_of(row0 & (NNODE - 1));
            const float s1 = s_of(rowB & (NNODE - 1));
            #pragma unroll
            for (int nb = 0; nb < 4; nb++) {
                const int col = ncol + wn * 32 + nb * 8 + tig * 2;
                const float bv0 = __ldg(bv + col), bv1 = __ldg(bv + col + 1);
                const float bg0 = __ldg(bg1 + col), bg1v = __ldg(bg1 + col + 1);
                float v0 = fmaxf(acc[mi][nb][0] + fmaf(s0, bv0, bg0), 0.f);
                float v1 = fmaxf(acc[mi][nb][1] + fmaf(s0, bv1, bg1v), 0.f);
                float v2 = fmaxf(acc[mi][nb][2] + fmaf(s1, bv0, bg0), 0.f);
                float v3 = fmaxf(acc[mi][nb][3] + fmaf(s1, bv1, bg1v), 0.f);
                float r0, r1;
                uint32_t h0 = pk_hi(v0, v1, r0, r1);
                uint32_t l0 = pk(r0, r1);
                uint32_t h1_ = pk_hi(v2, v3, r0, r1);
                uint32_t l1 = pk(r0, r1);
                *(uint32_t*)(Hh + (size_t)row0 * 512 + col) = h0;
                *(uint32_t*)(Hl + (size_t)row0 * 512 + col) = l0;
                *(uint32_t*)(Hh + (size_t)rowB * 512 + col) = h1_;
                *(uint32_t*)(Hl + (size_t)rowB * 512 + col) = l1;
            }
        }
        return;
    }

    float rsum[4][2], rq[4][2];
    #pragma unroll
    for (int nb = 0; nb < 4; nb++) { rsum[nb][0] = rsum[nb][1] = rq[nb][0] = rq[nb][1] = 0.f; }

    #pragma unroll
    for (int mi = 0; mi < 4; mi++) {
        const int row0 = mtile * 128 + wm * 64 + mi * 16 + gid;
        #pragma unroll
        for (int nb = 0; nb < 4; nb++) {
            const int col = ncol + wn * 32 + nb * 8 + tig * 2;
            float b0 = 0.f, b1 = 0.f;
            if (mode & 4) { b0 = __ldg(bias0 + col); b1 = __ldg(bias0 + col + 1); }
            float v0 = acc[mi][nb][0] + b0, v1 = acc[mi][nb][1] + b1;
            float v2 = acc[mi][nb][2] + b0, v3 = acc[mi][nb][3] + b1;
            if (mode & 2) {
                v0 = fmaxf(v0, 0.f); v1 = fmaxf(v1, 0.f);
                v2 = fmaxf(v2, 0.f); v3 = fmaxf(v3, 0.f);
            }
            if (mode & 1) {
                *(float2*)(C0 + (size_t)row0 * 512 + col) = make_float2(v0, v1);
                *(float2*)(C0 + (size_t)(row0 + 8) * 512 + col) = make_float2(v2, v3);
            }
            if (mode & 8) {
                rsum[nb][0] += v0 + v2; rsum[nb][1] += v1 + v3;
                if (mode & 16) {
                    rq[nb][0] = fmaf(v0, v0, fmaf(v2, v2, rq[nb][0]));
                    rq[nb][1] = fmaf(v1, v1, fmaf(v3, v3, rq[nb][1]));
                }
            }
        }
    }

    if (mode & 8) {
        #pragma unroll
        for (int nb = 0; nb < 4; nb++)
            #pragma unroll
            for (int j = 0; j < 2; j++) {
                #pragma unroll
                for (int m = 4; m <= 16; m <<= 1) {
                    rsum[nb][j] += __shfl_xor_sync(0xffffffffu, rsum[nb][j], m);
                    rq[nb][j]   += __shfl_xor_sync(0xffffffffu, rq[nb][j], m);
                }
            }
        __syncthreads();
        float* red = (float*)smem;
        if (gid == 0) {
            #pragma unroll
            for (int nb = 0; nb < 4; nb++) {
                const int c = wn * 32 + nb * 8 + tig * 2;
                red[wm * 128 + c]     = rsum[nb][0];
                red[wm * 128 + c + 1] = rsum[nb][1];
                red[256 + wm * 128 + c]     = rq[nb][0];
                red[256 + wm * 128 + c + 1] = rq[nb][1];
            }
        }
        __syncthreads();
        if (tid < 128) {
            const float s = red[tid] + red[128 + tid];
            redS[(size_t)mtile * 512 + ncol + tid] = s;
            if (mode & 16) {
                const float q = red[256 + tid] + red[384 + tid];
                redQ[(size_t)mtile * 512 + ncol + tid] = q;
            }
        }
    }
}

// ---------------- convert+transpose weights (w_res -> blk0, w_g2 -> blk3) ------
__global__ void convert_w_kernel(const float* __restrict__ w0, const float* __restrict__ w3,
                                 __nv_bfloat16* __restrict__ wh, __nv_bfloat16* __restrict__ wl)
{
    __shared__ float t[32][33];
    const int wsel = blockIdx.z;
    const float* w = wsel == 0 ? w0 : w3;
    const size_t off = (size_t)(wsel == 0 ? 0 : 3) * CCH * CCH;
    __nv_bfloat16* oh = wh + off;
    __nv_bfloat16* ol = wl + off;
    const int n0 = blockIdx.x * 32;
    const int k0 = blockIdx.y * 32;
    const int tx = threadIdx.x, ty = threadIdx.y;
    #pragma unroll
    for (int j = 0; j < 4; j++)
        t[ty + j * 8][tx] = w[(size_t)(k0 + ty + j * 8) * 512 + n0 + tx];
    __syncthreads();
    #pragma unroll
    for (int j = 0; j < 4; j++) {
        const float v = t[tx][ty + j * 8];
        const __nv_bfloat16 hb = __float2bfloat16(v);
        oh[(size_t)(n0 + ty + j * 8) * 512 + k0 + tx] = hb;
        ol[(size_t)(n0 + ty + j * 8) * 512 + k0 + tx] = __float2bfloat16(v - __bfloat162float(hb));
    }
}

// ---------------- Wc = w_pre @ w_g1 -> blk1 (transposed split) ----------------
__global__ void wc_kernel(const float* __restrict__ wpre, const float* __restrict__ wg1,
                          __nv_bfloat16* __restrict__ wh, __nv_bfloat16* __restrict__ wl)
{
    __shared__ float sA[32][33];
    __shared__ float sB[32][33];
    const int n0 = blockIdx.x * 32, k0 = blockIdx.y * 32;
    const int tx = threadIdx.x, ty = threadIdx.y;
    float acc[4] = {0.f, 0.f, 0.f, 0.f};
    for (int j0 = 0; j0 < 512; j0 += 32) {
        #pragma unroll
        for (int q = 0; q < 4; q++) {
            sA[ty + 8 * q][tx] = wpre[(size_t)(k0 + ty + 8 * q) * 512 + j0 + tx];
            sB[ty + 8 * q][tx] = wg1[(size_t)(j0 + ty + 8 * q) * 512 + n0 + tx];
        }
        __syncthreads();
        #pragma unroll
        for (int jj = 0; jj < 32; jj++) {
            const float b = sB[jj][tx];
            #pragma unroll
            for (int q = 0; q < 4; q++) acc[q] = fmaf(sA[ty + 8 * q][jj], b, acc[q]);
        }
        __syncthreads();
    }
    __nv_bfloat16* oh = wh + (size_t)1 * CCH * CCH;
    __nv_bfloat16* ol = wl + (size_t)1 * CCH * CCH;
    #pragma unroll
    for (int q = 0; q < 4; q++) {
        const int k = k0 + ty + 8 * q, n = n0 + tx;
        const __nv_bfloat16 hb = __float2bfloat16(acc[q]);
        oh[(size_t)n * 512 + k] = hb;
        ol[(size_t)n * 512 + k] = __float2bfloat16(acc[q] - __bfloat162float(hb));
    }
}

// ---------------- bv = b_pre @ w_g1 ----------------
__global__ void bv_kernel(const float* __restrict__ bpre, const float* __restrict__ wg1,
                          float* __restrict__ bv)
{
    const int n = blockIdx.x * 256 + threadIdx.x;
    float s = 0.f;
    for (int j = 0; j < 512; j++) s = fmaf(bpre[j], wg1[(size_t)j * 512 + n], s);
    bv[n] = s;
}

// ---------------- agg_x: xa = Agg(x) (fp32 in -> split bf16 out) ---------------
__global__ void agg_x_kernel(const float* __restrict__ in,
                             __nv_bfloat16* __restrict__ oh, __nv_bfloat16* __restrict__ ol)
{
    const int idx = blockIdx.x * 256 + threadIdx.x;
    const int c4 = idx & 127;
    const int node = (idx >> 7) & (NNODE - 1);
    const int b = idx >> 19;
    const int r = node >> 6;
    const int cc = node & 63;

    const float4* base = (const float4*)in + (size_t)b * NNODE * 128 + c4;
    const float dg = degf(r, cc);
    const float di = dinvf(dg);

    float4 v = base[(size_t)node * 128];
    float ax = di * v.x, ay = di * v.y, az = di * v.z, aw = di * v.w;
    if (cc > 0) {
        const float dj = dinvf(degf(r, cc - 1));
        float4 w = base[(size_t)(node - 1) * 128];
        ax = fmaf(dj, w.x, ax); ay = fmaf(dj, w.y, ay); az = fmaf(dj, w.z, az); aw = fmaf(dj, w.w, aw);
    }
    if (cc < GW - 1) {
        const float dj = dinvf(degf(r, cc + 1));
        float4 w = base[(size_t)(node + 1) * 128];
        ax = fmaf(dj, w.x, ax); ay = fmaf(dj, w.y, ay); az = fmaf(dj, w.z, az); aw = fmaf(dj, w.w, aw);
    }
    if (r > 0) {
        const float dj = dinvf(degf(r - 1, cc));
        float4 w = base[(size_t)(node - GW) * 128];
        ax = fmaf(dj, w.x, ax); ay = fmaf(dj, w.y, ay); az = fmaf(dj, w.z, az); aw = fmaf(dj, w.w, aw);
    }
    if (r < GH - 1) {
        const float dj = dinvf(degf(r + 1, cc));
        float4 w = base[(size_t)(node + GW) * 128];
        ax = fmaf(dj, w.x, ax); ay = fmaf(dj, w.y, ay); az = fmaf(dj, w.z, az); aw = fmaf(dj, w.w, aw);
    }
    const float sc = di / dg;
    float r0, r1, r2, r3;
    uint2 hi, lo;
    hi.x = pk_hi(sc * ax, sc * ay, r0, r1);
    hi.y = pk_hi(sc * az, sc * aw, r2, r3);
    lo.x = pk(r0, r1);
    lo.y = pk(r2, r3);
    const size_t e = ((size_t)b * NNODE * CCH + (size_t)node * CCH) / 4 + c4;
    ((uint2*)oh)[e] = hi;
    ((uint2*)ol)[e] = lo;
}

// ---------------- agg_y: ya = Agg(h1) (split bf16 in -> split bf16 out) --------
__global__ void agg_y_kernel(const __nv_bfloat16* __restrict__ ih, const __nv_bfloat16* __restrict__ il,
                             __nv_bfloat16* __restrict__ oh, __nv_bfloat16* __restrict__ ol)
{
    const int idx = blockIdx.x * 256 + threadIdx.x;
    const int c4 = idx & 127;
    const int node = (idx >> 7) & (NNODE - 1);
    const int b = idx >> 19;
    const int r = node >> 6;
    const int cc = node & 63;

    const uint2* bh = (const uint2*)ih + (size_t)b * NNODE * 128 + c4;
    const uint2* bl = (const uint2*)il + (size_t)b * NNODE * 128 + c4;
    const float dg = degf(r, cc);
    const float di = dinvf(dg);

    float ax, ay, az, aw;
    {
        uint2 h = bh[(size_t)node * 128], l = bl[(size_t)node * 128];
        float f0, f1, f2, f3;
        unpk2(h.x, l.x, f0, f1);
        unpk2(h.y, l.y, f2, f3);
        ax = di * f0; ay = di * f1; az = di * f2; aw = di * f3;
    }
    #define NB(noff, DJ) do { \
        const float dj = (DJ); \
        uint2 h = bh[(size_t)(noff) * 128], l = bl[(size_t)(noff) * 128]; \
        float f0, f1, f2, f3; \
        unpk2(h.x, l.x, f0, f1); \
        unpk2(h.y, l.y, f2, f3); \
        ax = fmaf(dj, f0, ax); ay = fmaf(dj, f1, ay); \
        az = fmaf(dj, f2, az); aw = fmaf(dj, f3, aw); \
    } while (0)
    if (cc > 0)      NB(node - 1,  dinvf(degf(r, cc - 1)));
    if (cc < GW - 1) NB(node + 1,  dinvf(degf(r, cc + 1)));
    if (r > 0)       NB(node - GW, dinvf(degf(r - 1, cc)));
    if (r < GH - 1)  NB(node + GW, dinvf(degf(r + 1, cc)));
    #undef NB

    const float sc = di / dg;
    float r0, r1, r2, r3;
    uint2 hi, lo;
    hi.x = pk_hi(sc * ax, sc * ay, r0, r1);
    hi.y = pk_hi(sc * az, sc * aw, r2, r3);
    lo.x = pk(r0, r1);
    lo.y = pk(r2, r3);
    const size_t e = ((size_t)b * NNODE * CCH + (size_t)node * CCH) / 4 + c4;
    ((uint2*)oh)[e] = hi;
    ((uint2*)ol)[e] = lo;
}

// ---------------- BN1 from hp (256 mtile rows, 32 per batch) ----------------
__global__ void bn1_kernel(const float* __restrict__ hp,
                           const float* __restrict__ g1, const float* __restrict__ beta1,
                           float* __restrict__ xg)
{
    const int c = blockIdx.x * 128 + threadIdx.x;
    float pooled[BATCH];
    float mu = 0.f;
    #pragma unroll
    for (int b = 0; b < BATCH; b++) {
        float s = 0.f;
        #pragma unroll 8
        for (int k = 0; k < 32; k++) s += hp[(size_t)(b * 32 + k) * CCH + c];
        pooled[b] = s * (1.f / (float)NNODE);
        mu += pooled[b];
    }
    mu *= (1.f / (float)BATCH);
    float var = 0.f;
    #pragma unroll
    for (int b = 0; b < BATCH; b++) { const float d = pooled[b] - mu; var = fmaf(d, d, var); }
    var *= (1.f / (float)BATCH);
    const float inv = rsqrtf(var + EPSV);
    const float ga = g1[c], be = beta1[c];
    #pragma unroll
    for (int b = 0; b < BATCH; b++)
        xg[b * CCH + c] = (pooled[b] - mu) * inv * ga + be;
}

// ---------------- BN2 scale/shift ----------------
__global__ void stats_reduce_kernel(const float* __restrict__ rs, const float* __restrict__ rq,
                                    const float* __restrict__ xg,
                                    const float* __restrict__ g2, const float* __restrict__ beta2,
                                    float* __restrict__ scale, float* __restrict__ shift)
{
    const int c = blockIdx.x * 128 + threadIdx.x;
    float S = 0.f, Q = 0.f;
    #pragma unroll
    for (int b = 0; b < BATCH; b++) {
        float sb = 0.f, qb = 0.f;
        #pragma unroll 8
        for (int k = 0; k < 32; k++) {
            const size_t idx = (size_t)(b * 32 + k) * CCH + c;
            sb += rs[idx]; qb += rq[idx];
        }
        const float xv = xg[b * CCH + c];
        S += sb + 4096.f * xv;
        Q += qb + 2.f * xv * sb + 4096.f * xv * xv;
    }
    const float mu = S * (1.f / (float)MROWS);
    float var = Q * (1.f / (float)MROWS) - mu * mu;
    var = fmaxf(var, 0.f);
    const float inv = rsqrtf(var + EPSV);
    const float sc = inv * g2[c];
    scale[c] = sc;
    shift[c] = beta2[c] - mu * sc;
}

// ---------------- final: BN2 apply + transpose ----------------
__global__ void final_kernel(const float* __restrict__ res, const float* __restrict__ xg,
                             const float* __restrict__ scale, const float* __restrict__ shift,
                             float* __restrict__ out)
{
    __shared__ float tile[32][33];
    const int b = blockIdx.z;
    const int n0 = blockIdx.x * 32;
    const int c0 = blockIdx.y * 32;
    const int tx = threadIdx.x, ty = threadIdx.y;
    #pragma unroll
    for (int k = 0; k < 4; k++) {
        const int n = n0 + ty + k * 8;
        const int c = c0 + tx;
        tile[ty + k * 8][tx] = res[((size_t)b * NNODE + n) * CCH + c] + xg[b * CCH + c];
    }
    __syncthreads();
    #pragma unroll
    for (int k = 0; k < 4; k++) {
        const int c = c0 + ty + k * 8;
        const int n = n0 + tx;
        out[((size_t)b * CCH + c) * NNODE + n] = tile[tx][ty + k * 8] * scale[c] + shift[c];
    }
}

// ---------------- launch ----------------
extern "C" void kernel_launch(void* const* d_in, const int* in_sizes, int n_in,
                              void* d_out, int out_size)
{
    const float* x = nullptr;
    const float* w[4] = {nullptr, nullptr, nullptr, nullptr};
    const float* v[7] = {nullptr, nullptr, nullptr, nullptr, nullptr, nullptr, nullptr};
    int wi = 0, vi = 0;
    for (int i = 0; i < n_in; i++) {
        const int sz = in_sizes[i];
        if (sz == MROWS * CCH) { if (!x) x = (const float*)d_in[i]; }
        else if (sz == CCH * CCH) { if (wi < 4) w[wi++] = (const float*)d_in[i]; }
        else if (sz == CCH) { if (vi < 7) v[vi++] = (const float*)d_in[i]; }
    }
    const float* b_pre = v[0]; const float* b_g1 = v[1]; const float* b_g2 = v[2];
    const float* g1 = v[3];    const float* beta1 = v[4];
    const float* g2 = v[5];    const float* beta2 = v[6];

    float *p_res, *p_hp, *p_rs, *p_rq, *p_xg, *p_bv, *p_sc, *p_sh;
    __nv_bfloat16 *p_xah, *p_xal, *p_h1h, *p_h1l, *p_yh, *p_yl, *p_wh, *p_wl;
    cudaGetSymbolAddress((void**)&p_res, g_res);
    cudaGetSymbolAddress((void**)&p_xah, g_xah);
    cudaGetSymbolAddress((void**)&p_xal, g_xal);
    cudaGetSymbolAddress((void**)&p_h1h, g_h1h);
    cudaGetSymbolAddress((void**)&p_h1l, g_h1l);
    cudaGetSymbolAddress((void**)&p_yh, g_yh);
    cudaGetSymbolAddress((void**)&p_yl, g_yl);
    cudaGetSymbolAddress((void**)&p_wh, g_wh);
    cudaGetSymbolAddress((void**)&p_wl, g_wl);
    cudaGetSymbolAddress((void**)&p_hp, g_hp);
    cudaGetSymbolAddress((void**)&p_rs, g_rs);
    cudaGetSymbolAddress((void**)&p_rq, g_rq);
    cudaGetSymbolAddress((void**)&p_xg, g_xg);
    cudaGetSymbolAddress((void**)&p_bv, g_bv);
    cudaGetSymbolAddress((void**)&p_sc, g_scale);
    cudaGetSymbolAddress((void**)&p_sh, g_shift);

    float* out = (float*)d_out;

    cudaFuncSetAttribute(gemm_mma<0>, cudaFuncAttributeMaxDynamicSharedMemorySize, (int)GEMM_SMEM);
    cudaFuncSetAttribute(gemm_mma<1>, cudaFuncAttributeMaxDynamicSharedMemorySize, (int)GEMM_SMEM);

    const int agg_blocks = (BATCH * NNODE * (CCH / 4)) / 256;
    const size_t WB = (size_t)CCH * CCH;

    // weight prep: w_res -> blk0, w_g2 -> blk3, Wc -> blk1, bv
    convert_w_kernel<<<dim3(16, 16, 2), dim3(32, 8)>>>(w[0], w[3], p_wh, p_wl);
    wc_kernel<<<dim3(16, 16), dim3(32, 8)>>>(w[1], w[2], p_wh, p_wl);
    bv_kernel<<<2, 256>>>(b_pre, w[2], p_bv);

    // xa = Agg(x) -> split bf16
    agg_x_kernel<<<agg_blocks, 256>>>(x, p_xah, p_xal);

    // dual GEMM: ntile 0..3 -> res = x@w_res (fp32 A, store + stats partials)
    //            ntile 4..7 -> h1 = relu(xa@Wc + s*bv + b_g1) -> split bf16
    gemm_mma<1><<<dim3(8, 256), 256, GEMM_SMEM>>>(
        x, p_xah, p_xal, p_wh, p_wl,
        p_res, nullptr, p_rs, p_rq,
        p_h1h, p_h1l, p_bv, b_g1,
        /*mode0=*/1 | 8 | 16, /*mode1=*/32);

    // ya = Agg(h1) -> split bf16
    agg_y_kernel<<<agg_blocks, 256>>>(p_h1h, p_h1l, p_yh, p_yl);

    // h2 colsums: relu(ya@w_g2 + b_g2) -> hp partials, no store
    gemm_mma<0><<<dim3(4, 256), 256, GEMM_SMEM>>>(
        nullptr, p_yh, p_yl, p_wh + 3 * WB, p_wl + 3 * WB,
        nullptr, b_g2, p_hp, nullptr,
        nullptr, nullptr, nullptr, nullptr,
        /*mode0=*/2 | 4 | 8, /*mode1=*/0);

    bn1_kernel<<<4, 128>>>(p_hp, g1, beta1, p_xg);
    stats_reduce_kernel<<<4, 128>>>(p_rs, p_rq, p_xg, g2, beta2, p_sc, p_sh);
    final_kernel<<<dim3(NNODE / 32, CCH / 32, BATCH), dim3(32, 8)>>>(p_res, p_xg, p_sc, p_sh, out);
}

// round 11
// speedup vs baseline: 1.2851x; 1.0249x over previous
#include <cuda_runtime.h>
#include <cuda_bf16.h>
#include <cstdint>
#include <math.h>

#define BATCH 8
#define GH 64
#define GW 64
#define NNODE 4096
#define CCH 512
#define MROWS (BATCH * NNODE)
#define EPSV 1e-5f

// ---------------- scratch ----------------
__device__ float g_res[MROWS * CCH];
__device__ __nv_bfloat16 g_xah[MROWS * CCH];
__device__ __nv_bfloat16 g_xal[MROWS * CCH];
__device__ __nv_bfloat16 g_h1h[MROWS * CCH];
__device__ __nv_bfloat16 g_h1l[MROWS * CCH];
__device__ __nv_bfloat16 g_yh[MROWS * CCH];
__device__ __nv_bfloat16 g_yl[MROWS * CCH];
__device__ __nv_bfloat16 g_wh[4 * CCH * CCH];
__device__ __nv_bfloat16 g_wl[4 * CCH * CCH];
__device__ float g_hp[256 * CCH];
__device__ float g_rs[256 * CCH];
__device__ float g_rq[256 * CCH];
__device__ float g_xg[BATCH * CCH];
__device__ float g_bv[CCH];
__device__ float g_scale[CCH];
__device__ float g_shift[CCH];

// ---------------- helpers ----------------
__device__ __forceinline__ uint32_t smem_u32(const void* p) {
    uint32_t a;
    asm("{ .reg .u64 t; cvta.to.shared.u64 t, %1; cvt.u32.u64 %0, t; }" : "=r"(a) : "l"(p));
    return a;
}
__device__ __forceinline__ void ldsm_x4(uint32_t addr, uint32_t* r) {
    asm volatile("ldmatrix.sync.aligned.m8n8.x4.shared.b16 {%0,%1,%2,%3}, [%4];"
                 : "=r"(r[0]), "=r"(r[1]), "=r"(r[2]), "=r"(r[3]) : "r"(addr));
}
__device__ __forceinline__ void mma16816(float* c, const uint32_t* a, const uint32_t* b) {
    asm volatile("mma.sync.aligned.m16n8k16.row.col.f32.bf16.bf16.f32 "
                 "{%0,%1,%2,%3}, {%4,%5,%6,%7}, {%8,%9}, {%0,%1,%2,%3};"
                 : "+f"(c[0]), "+f"(c[1]), "+f"(c[2]), "+f"(c[3])
                 : "r"(a[0]), "r"(a[1]), "r"(a[2]), "r"(a[3]), "r"(b[0]), "r"(b[1]));
}
__device__ __forceinline__ void cp16(uint32_t dst, const void* src) {
    asm volatile("cp.async.cg.shared.global [%0], [%1], 16;" :: "r"(dst), "l"(src) : "memory");
}
#define CP_COMMIT() asm volatile("cp.async.commit_group;" ::: "memory")
#define CP_WAIT0()  asm volatile("cp.async.wait_group 0;" ::: "memory")
#define CP_WAIT1()  asm volatile("cp.async.wait_group 1;" ::: "memory")

__device__ __forceinline__ uint32_t pk_hi(float x, float y, float& rx, float& ry) {
    __nv_bfloat16 hx = __float2bfloat16(x), hy = __float2bfloat16(y);
    rx = x - __bfloat162float(hx);
    ry = y - __bfloat162float(hy);
    return (uint32_t)__bfloat16_as_ushort(hx) | ((uint32_t)__bfloat16_as_ushort(hy) << 16);
}
__device__ __forceinline__ uint32_t pk(float x, float y) {
    return (uint32_t)__bfloat16_as_ushort(__float2bfloat16(x))
         | ((uint32_t)__bfloat16_as_ushort(__float2bfloat16(y)) << 16);
}
__device__ __forceinline__ void unpk2(uint32_t h, uint32_t l, float& a, float& b) {
    a = __bfloat162float(__ushort_as_bfloat16((unsigned short)(h & 0xffff)))
      + __bfloat162float(__ushort_as_bfloat16((unsigned short)(l & 0xffff)));
    b = __bfloat162float(__ushort_as_bfloat16((unsigned short)(h >> 16)))
      + __bfloat162float(__ushort_as_bfloat16((unsigned short)(l >> 16)));
}

// ---------------- GCN geometry ----------------
__device__ __forceinline__ float degf(int r, int c) {
    return 1.f + (float)(c > 0) + (float)(c < GW - 1) + (float)(r > 0) + (float)(r < GH - 1);
}
__device__ __forceinline__ float dinvf(float dg) {
    return dg == 3.f ? 0.57735026918962576f : (dg == 4.f ? 0.5f : 0.44721359549995794f);
}
__device__ __forceinline__ float s_of(int node) {
    const int r = node >> 6, c = node & 63;
    const float dg = degf(r, c);
    const float di = dinvf(dg);
    float sum = di;
    if (c > 0)      sum += dinvf(degf(r, c - 1));
    if (c < GW - 1) sum += dinvf(degf(r, c + 1));
    if (r > 0)      sum += dinvf(degf(r - 1, c));
    if (r < GH - 1) sum += dinvf(degf(r + 1, c));
    return di / dg * sum;
}

// ---------------- mma.sync split-bf16 GEMM, 128x128 tile, 3-stage SW128 --------
// mode bits: 1=store C(fp32), 2=relu, 4=bias0, 8=colsum partials, 16=also sumsq,
//            32=h1 epilogue (relu(acc + s_row*bv + bg1) -> split-bf16, smem-staged)
#define TILE16 16384u
#define STAGEB 32768u
#define GEMM_SMEM (3u * STAGEB)

template<int AFP32>
__global__ __launch_bounds__(256, 2)
void gemm_mma(const float* __restrict__ Ax,
              const __nv_bfloat16* __restrict__ Ah, const __nv_bfloat16* __restrict__ Al,
              const __nv_bfloat16* __restrict__ Bh, const __nv_bfloat16* __restrict__ Bl,
              float* __restrict__ C0, const float* __restrict__ bias0,
              float* __restrict__ redS, float* __restrict__ redQ,
              __nv_bfloat16* __restrict__ Hh, __nv_bfloat16* __restrict__ Hl,
              const float* __restrict__ bv, const float* __restrict__ bg1,
              int mode0, int mode1)
{
    extern __shared__ __align__(128) char smem[];
    const uint32_t sb = smem_u32(smem);
    const int tid = threadIdx.x;
    const int wid = tid >> 5;
    const int lane = tid & 31;
    const int wm = wid & 1;
    const int wn = wid >> 1;
    const int mtile = blockIdx.y;
    const int ntile = blockIdx.x;
    const bool f32p = AFP32 && (ntile < 4);

    const __nv_bfloat16* src0 = Ah + (size_t)mtile * 128 * 512;
    const __nv_bfloat16* src1 = Al + (size_t)mtile * 128 * 512;
    const float* srcx = Ax + (size_t)mtile * 128 * 512;
    const __nv_bfloat16* src2 = Bh + (size_t)ntile * 128 * 512;
    const __nv_bfloat16* src3 = Bl + (size_t)ntile * 128 * 512;

    float acc[4][4][4];
    #pragma unroll
    for (int i = 0; i < 4; i++)
        #pragma unroll
        for (int j = 0; j < 4; j++)
            #pragma unroll
            for (int k = 0; k < 4; k++) acc[i][j][k] = 0.f;

    const int lr = lane & 15;
    const int lk = lane >> 4;
    const int bn = (lane & 7) + ((lane >> 4) << 3);
    const int bkc2 = (lane >> 3) & 1;

    const int au_row[2] = { tid >> 2, (256 + tid) >> 2 };
    const int au_ch = tid & 3;
    float4 ra[2][2];

    #define LOAD_STAGE_BF16(kc, st) do { \
        const int _kc = (kc); const uint32_t _b = sb + (uint32_t)(st) * STAGEB; \
        _Pragma("unroll") \
        for (int p = 0; p < 8; p++) { \
            const int id = p * 256 + tid; \
            const int sel = id >> 10; \
            const int e = id & 1023; \
            const int row = e >> 3, j = e & 7; \
            const uint32_t dst = _b + (uint32_t)sel * TILE16 + (uint32_t)row * 128u \
                               + (uint32_t)((j ^ (row & 7)) << 4); \
            const __nv_bfloat16* s = (sel == 0 ? (j < 4 ? src0 : src1) : (j < 4 ? src2 : src3)) \
                                     + (size_t)row * 512 + (size_t)_kc * 32 + (j & 3) * 8; \
            cp16(dst, s); \
        } \
        CP_COMMIT(); \
    } while (0)

    #define LOAD_STAGE_B(kc, st) do { \
        const int _kc = (kc); const uint32_t _b = sb + (uint32_t)(st) * STAGEB + TILE16; \
        _Pragma("unroll") \
        for (int p = 0; p < 4; p++) { \
            const int id = p * 256 + tid; \
            const int row = id >> 3, j = id & 7; \
            const uint32_t dst = _b + (uint32_t)row * 128u + (uint32_t)((j ^ (row & 7)) << 4); \
            const __nv_bfloat16* s = (j < 4 ? src2 : src3) \
                                     + (size_t)row * 512 + (size_t)_kc * 32 + (j & 3) * 8; \
            cp16(dst, s); \
        } \
        CP_COMMIT(); \
    } while (0)

    #define LOAD_A_F32(kc) do { \
        const int _kc = (kc); \
        _Pragma("unroll") \
        for (int i = 0; i < 2; i++) { \
            const float* s = srcx + (size_t)au_row[i] * 512 + (size_t)_kc * 32 + au_ch * 8; \
            ra[i][0] = *(const float4*)s; \
            ra[i][1] = *(const float4*)(s + 4); \
        } \
    } while (0)

    #define STORE_A_F32(st) do { \
        const uint32_t _o = (uint32_t)(st) * STAGEB; \
        _Pragma("unroll") \
        for (int i = 0; i < 2; i++) { \
            float r0, r1, r2, r3, r4, r5, r6, r7; \
            uint4 hi, lo; \
            hi.x = pk_hi(ra[i][0].x, ra[i][0].y, r0, r1); \
            hi.y = pk_hi(ra[i][0].z, ra[i][0].w, r2, r3); \
            hi.z = pk_hi(ra[i][1].x, ra[i][1].y, r4, r5); \
            hi.w = pk_hi(ra[i][1].z, ra[i][1].w, r6, r7); \
            lo.x = pk(r0, r1); lo.y = pk(r2, r3); lo.z = pk(r4, r5); lo.w = pk(r6, r7); \
            const int sw = au_row[i] & 7; \
            *(uint4*)(smem + _o + (uint32_t)au_row[i] * 128u + (uint32_t)((au_ch ^ sw) << 4)) = hi; \
            *(uint4*)(smem + _o + (uint32_t)au_row[i] * 128u + (uint32_t)(((au_ch + 4) ^ sw) << 4)) = lo; \
        } \
    } while (0)

    if (f32p) {
        LOAD_A_F32(0); STORE_A_F32(0);
        LOAD_STAGE_B(0, 0);
        LOAD_STAGE_B(1, 1);
    } else {
        LOAD_STAGE_BF16(0, 0);
        LOAD_STAGE_BF16(1, 1);
    }

    #pragma unroll 1
    for (int kc = 0; kc < 16; kc++) {
        if (kc < 15) { CP_WAIT1(); } else { CP_WAIT0(); }
        __syncthreads();
        const int st = kc % 3;
        if (kc + 2 < 16) {
            const int st2 = (kc + 2) % 3;
            if (f32p) LOAD_STAGE_B(kc + 2, st2);
            else      LOAD_STAGE_BF16(kc + 2, st2);
        }
        if (f32p && kc + 1 < 16) LOAD_A_F32(kc + 1);

        const uint32_t baseA = sb + (uint32_t)st * STAGEB;
        const uint32_t baseB = baseA + TILE16;
        #pragma unroll
        for (int ks = 0; ks < 2; ks++) {
            uint32_t ah[4][4], al[4][4];
            #pragma unroll
            for (int mi = 0; mi < 4; mi++) {
                const int R = wm * 64 + mi * 16 + lr;
                const int sw = R & 7;
                const int ch = 2 * ks + lk;
                ldsm_x4(baseA + (uint32_t)R * 128u + (uint32_t)((ch ^ sw) << 4), ah[mi]);
                ldsm_x4(baseA + (uint32_t)R * 128u + (uint32_t)(((ch + 4) ^ sw) << 4), al[mi]);
            }
            #pragma unroll
            for (int np = 0; np < 2; np++) {
                uint32_t bh[2][2], bl[2][2];
                const int R = wn * 32 + np * 16 + bn;
                const int sw = R & 7;
                const int ch = 2 * ks + bkc2;
                uint32_t r[4];
                ldsm_x4(baseB + (uint32_t)R * 128u + (uint32_t)((ch ^ sw) << 4), r);
                bh[0][0] = r[0]; bh[0][1] = r[1]; bh[1][0] = r[2]; bh[1][1] = r[3];
                ldsm_x4(baseB + (uint32_t)R * 128u + (uint32_t)(((ch + 4) ^ sw) << 4), r);
                bl[0][0] = r[0]; bl[0][1] = r[1]; bl[1][0] = r[2]; bl[1][1] = r[3];
                #pragma unroll
                for (int mi = 0; mi < 4; mi++)
                    #pragma unroll
                    for (int b2 = 0; b2 < 2; b2++) {
                        const int nb = np * 2 + b2;
                        mma16816(acc[mi][nb], ah[mi], bh[b2]);
                        mma16816(acc[mi][nb], ah[mi], bl[b2]);
                        mma16816(acc[mi][nb], al[mi], bh[b2]);
                    }
            }
        }
        if (f32p && kc + 1 < 16) STORE_A_F32((kc + 1) % 3);
    }

    // ---------------- epilogue ----------------
    const int mode = (ntile >= 4) ? mode1 : mode0;
    const int ncol = (ntile & 3) * 128;
    const int gid = lane >> 2;
    const int tig = lane & 3;

    if (mode & 32) {
        // h1 = relu(acc + s_row*bv + bg1) -> split-bf16 via smem-staged coalesced stores
        __syncthreads();  // pipeline stages dead
        uint32_t* sh = (uint32_t*)smem;             // [128][64] hi, bank-swizzled
        uint32_t* sl = (uint32_t*)(smem + 32768);   // lo
        #pragma unroll
        for (int mi = 0; mi < 4; mi++) {
            const int rl0 = wm * 64 + mi * 16 + gid;
            const int rl1 = rl0 + 8;
            const int grow0 = mtile * 128 + rl0;
            const float s0 = s_of(grow0 & (NNODE - 1));
            const float s1 = s_of((grow0 + 8) & (NNODE - 1));
            #pragma unroll
            for (int nb = 0; nb < 4; nb++) {
                const int col = ncol + wn * 32 + nb * 8 + tig * 2;
                const float bv0 = __ldg(bv + col), bv1 = __ldg(bv + col + 1);
                const float bg0 = __ldg(bg1 + col), bg1v = __ldg(bg1 + col + 1);
                float v0 = fmaxf(acc[mi][nb][0] + fmaf(s0, bv0, bg0), 0.f);
                float v1 = fmaxf(acc[mi][nb][1] + fmaf(s0, bv1, bg1v), 0.f);
                float v2 = fmaxf(acc[mi][nb][2] + fmaf(s1, bv0, bg0), 0.f);
                float v3 = fmaxf(acc[mi][nb][3] + fmaf(s1, bv1, bg1v), 0.f);
                float r0, r1;
                uint32_t h0 = pk_hi(v0, v1, r0, r1);
                uint32_t l0 = pk(r0, r1);
                uint32_t h1_ = pk_hi(v2, v3, r0, r1);
                uint32_t l1 = pk(r0, r1);
                const int c32 = wn * 16 + nb * 4 + tig;
                const int a0 = rl0 * 64 + (c32 ^ ((rl0 & 15) << 2));
                const int a1 = rl1 * 64 + (c32 ^ ((rl1 & 15) << 2));
                sh[a0] = h0; sl[a0] = l0;
                sh[a1] = h1_; sl[a1] = l1;
            }
        }
        __syncthreads();
        #pragma unroll
        for (int i = 0; i < 8; i++) {
            const int u = i * 256 + tid;     // uint4 tile index 0..2047
            const int row = u >> 4;
            const int c4 = u & 15;
            const int c4s = (c4 ^ (row & 15)) << 2;
            uint4 hv = *(uint4*)&sh[row * 64 + c4s];
            uint4 lv = *(uint4*)&sl[row * 64 + c4s];
            const size_t g = (size_t)(mtile * 128 + row) * 512 + ncol + c4 * 8;
            *(uint4*)(Hh + g) = hv;
            *(uint4*)(Hl + g) = lv;
        }
        return;
    }

    float rsum[4][2], rq[4][2];
    #pragma unroll
    for (int nb = 0; nb < 4; nb++) { rsum[nb][0] = rsum[nb][1] = rq[nb][0] = rq[nb][1] = 0.f; }

    #pragma unroll
    for (int mi = 0; mi < 4; mi++) {
        const int row0 = mtile * 128 + wm * 64 + mi * 16 + gid;
        #pragma unroll
        for (int nb = 0; nb < 4; nb++) {
            const int col = ncol + wn * 32 + nb * 8 + tig * 2;
            float b0 = 0.f, b1 = 0.f;
            if (mode & 4) { b0 = __ldg(bias0 + col); b1 = __ldg(bias0 + col + 1); }
            float v0 = acc[mi][nb][0] + b0, v1 = acc[mi][nb][1] + b1;
            float v2 = acc[mi][nb][2] + b0, v3 = acc[mi][nb][3] + b1;
            if (mode & 2) {
                v0 = fmaxf(v0, 0.f); v1 = fmaxf(v1, 0.f);
                v2 = fmaxf(v2, 0.f); v3 = fmaxf(v3, 0.f);
            }
            if (mode & 1) {
                *(float2*)(C0 + (size_t)row0 * 512 + col) = make_float2(v0, v1);
                *(float2*)(C0 + (size_t)(row0 + 8) * 512 + col) = make_float2(v2, v3);
            }
            if (mode & 8) {
                rsum[nb][0] += v0 + v2; rsum[nb][1] += v1 + v3;
                if (mode & 16) {
                    rq[nb][0] = fmaf(v0, v0, fmaf(v2, v2, rq[nb][0]));
                    rq[nb][1] = fmaf(v1, v1, fmaf(v3, v3, rq[nb][1]));
                }
            }
        }
    }

    if (mode & 8) {
        #pragma unroll
        for (int nb = 0; nb < 4; nb++)
            #pragma unroll
            for (int j = 0; j < 2; j++) {
                #pragma unroll
                for (int m = 4; m <= 16; m <<= 1) {
                    rsum[nb][j] += __shfl_xor_sync(0xffffffffu, rsum[nb][j], m);
                    rq[nb][j]   += __shfl_xor_sync(0xffffffffu, rq[nb][j], m);
                }
            }
        __syncthreads();
        float* red = (float*)smem;
        if (gid == 0) {
            #pragma unroll
            for (int nb = 0; nb < 4; nb++) {
                const int c = wn * 32 + nb * 8 + tig * 2;
                red[wm * 128 + c]     = rsum[nb][0];
                red[wm * 128 + c + 1] = rsum[nb][1];
                red[256 + wm * 128 + c]     = rq[nb][0];
                red[256 + wm * 128 + c + 1] = rq[nb][1];
            }
        }
        __syncthreads();
        if (tid < 128) {
            const float s = red[tid] + red[128 + tid];
            redS[(size_t)mtile * 512 + ncol + tid] = s;
            if (mode & 16) {
                const float q = red[256 + tid] + red[384 + tid];
                redQ[(size_t)mtile * 512 + ncol + tid] = q;
            }
        }
    }
}

// ---------------- convert+transpose weights (w_res -> blk0, w_g2 -> blk3) ------
__global__ void convert_w_kernel(const float* __restrict__ w0, const float* __restrict__ w3,
                                 __nv_bfloat16* __restrict__ wh, __nv_bfloat16* __restrict__ wl)
{
    __shared__ float t[32][33];
    const int wsel = blockIdx.z;
    const float* w = wsel == 0 ? w0 : w3;
    const size_t off = (size_t)(wsel == 0 ? 0 : 3) * CCH * CCH;
    __nv_bfloat16* oh = wh + off;
    __nv_bfloat16* ol = wl + off;
    const int n0 = blockIdx.x * 32;
    const int k0 = blockIdx.y * 32;
    const int tx = threadIdx.x, ty = threadIdx.y;
    #pragma unroll
    for (int j = 0; j < 4; j++)
        t[ty + j * 8][tx] = w[(size_t)(k0 + ty + j * 8) * 512 + n0 + tx];
    __syncthreads();
    #pragma unroll
    for (int j = 0; j < 4; j++) {
        const float v = t[tx][ty + j * 8];
        const __nv_bfloat16 hb = __float2bfloat16(v);
        oh[(size_t)(n0 + ty + j * 8) * 512 + k0 + tx] = hb;
        ol[(size_t)(n0 + ty + j * 8) * 512 + k0 + tx] = __float2bfloat16(v - __bfloat162float(hb));
    }
}

// ---------------- Wc = w_pre @ w_g1 -> blk1 (transposed split) ----------------
__global__ void wc_kernel(const float* __restrict__ wpre, const float* __restrict__ wg1,
                          __nv_bfloat16* __restrict__ wh, __nv_bfloat16* __restrict__ wl)
{
    __shared__ float sA[32][33];
    __shared__ float sB[32][33];
    const int n0 = blockIdx.x * 32, k0 = blockIdx.y * 32;
    const int tx = threadIdx.x, ty = threadIdx.y;
    float acc[4] = {0.f, 0.f, 0.f, 0.f};
    for (int j0 = 0; j0 < 512; j0 += 32) {
        #pragma unroll
        for (int q = 0; q < 4; q++) {
            sA[ty + 8 * q][tx] = wpre[(size_t)(k0 + ty + 8 * q) * 512 + j0 + tx];
            sB[ty + 8 * q][tx] = wg1[(size_t)(j0 + ty + 8 * q) * 512 + n0 + tx];
        }
        __syncthreads();
        #pragma unroll
        for (int jj = 0; jj < 32; jj++) {
            const float b = sB[jj][tx];
            #pragma unroll
            for (int q = 0; q < 4; q++) acc[q] = fmaf(sA[ty + 8 * q][jj], b, acc[q]);
        }
        __syncthreads();
    }
    __nv_bfloat16* oh = wh + (size_t)1 * CCH * CCH;
    __nv_bfloat16* ol = wl + (size_t)1 * CCH * CCH;
    #pragma unroll
    for (int q = 0; q < 4; q++) {
        const int k = k0 + ty + 8 * q, n = n0 + tx;
        const __nv_bfloat16 hb = __float2bfloat16(acc[q]);
        oh[(size_t)n * 512 + k] = hb;
        ol[(size_t)n * 512 + k] = __float2bfloat16(acc[q] - __bfloat162float(hb));
    }
}

// ---------------- bv = b_pre @ w_g1 ----------------
__global__ void bv_kernel(const float* __restrict__ bpre, const float* __restrict__ wg1,
                          float* __restrict__ bv)
{
    const int n = blockIdx.x * 256 + threadIdx.x;
    float s = 0.f;
    for (int j = 0; j < 512; j++) s = fmaf(bpre[j], wg1[(size_t)j * 512 + n], s);
    bv[n] = s;
}

// ---------------- agg_x: xa = Agg(x), 8 ch/thread, uint4 stores ----------------
__global__ void agg_x_kernel(const float* __restrict__ in,
                             __nv_bfloat16* __restrict__ oh, __nv_bfloat16* __restrict__ ol)
{
    const int idx = blockIdx.x * 256 + threadIdx.x;
    const int c8 = idx & 63;
    const int node = (idx >> 6) & (NNODE - 1);
    const int b = idx >> 18;
    const int r = node >> 6;
    const int cc = node & 63;

    const float* base = in + (size_t)b * NNODE * 512 + c8 * 8;
    const float dg = degf(r, cc);
    const float di = dinvf(dg);

    float a[8];
    {
        const float* p = base + (size_t)node * 512;
        float4 u = *(const float4*)p, v = *(const float4*)(p + 4);
        a[0] = di * u.x; a[1] = di * u.y; a[2] = di * u.z; a[3] = di * u.w;
        a[4] = di * v.x; a[5] = di * v.y; a[6] = di * v.z; a[7] = di * v.w;
    }
    #define NBX(noff, DJ) do { \
        const float dj = (DJ); \
        const float* p = base + (size_t)(noff) * 512; \
        float4 u = *(const float4*)p, v = *(const float4*)(p + 4); \
        a[0] = fmaf(dj, u.x, a[0]); a[1] = fmaf(dj, u.y, a[1]); \
        a[2] = fmaf(dj, u.z, a[2]); a[3] = fmaf(dj, u.w, a[3]); \
        a[4] = fmaf(dj, v.x, a[4]); a[5] = fmaf(dj, v.y, a[5]); \
        a[6] = fmaf(dj, v.z, a[6]); a[7] = fmaf(dj, v.w, a[7]); \
    } while (0)
    if (cc > 0)      NBX(node - 1,  dinvf(degf(r, cc - 1)));
    if (cc < GW - 1) NBX(node + 1,  dinvf(degf(r, cc + 1)));
    if (r > 0)       NBX(node - GW, dinvf(degf(r - 1, cc)));
    if (r < GH - 1)  NBX(node + GW, dinvf(degf(r + 1, cc)));
    #undef NBX

    const float sc = di / dg;
    float r0, r1;
    uint4 hi, lo;
    hi.x = pk_hi(sc * a[0], sc * a[1], r0, r1); lo.x = pk(r0, r1);
    hi.y = pk_hi(sc * a[2], sc * a[3], r0, r1); lo.y = pk(r0, r1);
    hi.z = pk_hi(sc * a[4], sc * a[5], r0, r1); lo.z = pk(r0, r1);
    hi.w = pk_hi(sc * a[6], sc * a[7], r0, r1); lo.w = pk(r0, r1);
    const size_t e = (size_t)b * NNODE * 512 + (size_t)node * 512 + c8 * 8;
    *(uint4*)(oh + e) = hi;
    *(uint4*)(ol + e) = lo;
}

// ---------------- agg_y: ya = Agg(h1), 8 ch/thread ----------------
__global__ void agg_y_kernel(const __nv_bfloat16* __restrict__ ih, const __nv_bfloat16* __restrict__ il,
                             __nv_bfloat16* __restrict__ oh, __nv_bfloat16* __restrict__ ol)
{
    const int idx = blockIdx.x * 256 + threadIdx.x;
    const int c8 = idx & 63;
    const int node = (idx >> 6) & (NNODE - 1);
    const int b = idx >> 18;
    const int r = node >> 6;
    const int cc = node & 63;

    const uint4* bh = (const uint4*)ih + (size_t)b * NNODE * 64 + c8;
    const uint4* bl = (const uint4*)il + (size_t)b * NNODE * 64 + c8;
    const float dg = degf(r, cc);
    const float di = dinvf(dg);

    float a[8];
    {
        uint4 h = bh[(size_t)node * 64], l = bl[(size_t)node * 64];
        unpk2(h.x, l.x, a[0], a[1]); unpk2(h.y, l.y, a[2], a[3]);
        unpk2(h.z, l.z, a[4], a[5]); unpk2(h.w, l.w, a[6], a[7]);
        #pragma unroll
        for (int k = 0; k < 8; k++) a[k] *= di;
    }
    #define NBY(noff, DJ) do { \
        const float dj = (DJ); \
        uint4 h = bh[(size_t)(noff) * 64], l = bl[(size_t)(noff) * 64]; \
        float f0, f1; \
        unpk2(h.x, l.x, f0, f1); a[0] = fmaf(dj, f0, a[0]); a[1] = fmaf(dj, f1, a[1]); \
        unpk2(h.y, l.y, f0, f1); a[2] = fmaf(dj, f0, a[2]); a[3] = fmaf(dj, f1, a[3]); \
        unpk2(h.z, l.z, f0, f1); a[4] = fmaf(dj, f0, a[4]); a[5] = fmaf(dj, f1, a[5]); \
        unpk2(h.w, l.w, f0, f1); a[6] = fmaf(dj, f0, a[6]); a[7] = fmaf(dj, f1, a[7]); \
    } while (0)
    if (cc > 0)      NBY(node - 1,  dinvf(degf(r, cc - 1)));
    if (cc < GW - 1) NBY(node + 1,  dinvf(degf(r, cc + 1)));
    if (r > 0)       NBY(node - GW, dinvf(degf(r - 1, cc)));
    if (r < GH - 1)  NBY(node + GW, dinvf(degf(r + 1, cc)));
    #undef NBY

    const float sc = di / dg;
    float r0, r1;
    uint4 hi, lo;
    hi.x = pk_hi(sc * a[0], sc * a[1], r0, r1); lo.x = pk(r0, r1);
    hi.y = pk_hi(sc * a[2], sc * a[3], r0, r1); lo.y = pk(r0, r1);
    hi.z = pk_hi(sc * a[4], sc * a[5], r0, r1); lo.z = pk(r0, r1);
    hi.w = pk_hi(sc * a[6], sc * a[7], r0, r1); lo.w = pk(r0, r1);
    const size_t e = (size_t)b * NNODE * 512 + (size_t)node * 512 + c8 * 8;
    *(uint4*)(oh + e) = hi;
    *(uint4*)(ol + e) = lo;
}

// ---------------- BN1 from hp (256 mtile rows, 32 per batch) ----------------
__global__ void bn1_kernel(const float* __restrict__ hp,
                           const float* __restrict__ g1, const float* __restrict__ beta1,
                           float* __restrict__ xg)
{
    const int c = blockIdx.x * 128 + threadIdx.x;
    float pooled[BATCH];
    float mu = 0.f;
    #pragma unroll
    for (int b = 0; b < BATCH; b++) {
        float s = 0.f;
        #pragma unroll 8
        for (int k = 0; k < 32; k++) s += hp[(size_t)(b * 32 + k) * CCH + c];
        pooled[b] = s * (1.f / (float)NNODE);
        mu += pooled[b];
    }
    mu *= (1.f / (float)BATCH);
    float var = 0.f;
    #pragma unroll
    for (int b = 0; b < BATCH; b++) { const float d = pooled[b] - mu; var = fmaf(d, d, var); }
    var *= (1.f / (float)BATCH);
    const float inv = rsqrtf(var + EPSV);
    const float ga = g1[c], be = beta1[c];
    #pragma unroll
    for (int b = 0; b < BATCH; b++)
        xg[b * CCH + c] = (pooled[b] - mu) * inv * ga + be;
}

// ---------------- BN2 scale/shift ----------------
__global__ void stats_reduce_kernel(const float* __restrict__ rs, const float* __restrict__ rq,
                                    const float* __restrict__ xg,
                                    const float* __restrict__ g2, const float* __restrict__ beta2,
                                    float* __restrict__ scale, float* __restrict__ shift)
{
    const int c = blockIdx.x * 128 + threadIdx.x;
    float S = 0.f, Q = 0.f;
    #pragma unroll
    for (int b = 0; b < BATCH; b++) {
        float sb = 0.f, qb = 0.f;
        #pragma unroll 8
        for (int k = 0; k < 32; k++) {
            const size_t idx = (size_t)(b * 32 + k) * CCH + c;
            sb += rs[idx]; qb += rq[idx];
        }
        const float xv = xg[b * CCH + c];
        S += sb + 4096.f * xv;
        Q += qb + 2.f * xv * sb + 4096.f * xv * xv;
    }
    const float mu = S * (1.f / (float)MROWS);
    float var = Q * (1.f / (float)MROWS) - mu * mu;
    var = fmaxf(var, 0.f);
    const float inv = rsqrtf(var + EPSV);
    const float sc = inv * g2[c];
    scale[c] = sc;
    shift[c] = beta2[c] - mu * sc;
}

// ---------------- final: BN2 apply + transpose ----------------
__global__ void final_kernel(const float* __restrict__ res, const float* __restrict__ xg,
                             const float* __restrict__ scale, const float* __restrict__ shift,
                             float* __restrict__ out)
{
    __shared__ float tile[32][33];
    const int b = blockIdx.z;
    const int n0 = blockIdx.x * 32;
    const int c0 = blockIdx.y * 32;
    const int tx = threadIdx.x, ty = threadIdx.y;
    #pragma unroll
    for (int k = 0; k < 4; k++) {
        const int n = n0 + ty + k * 8;
        const int c = c0 + tx;
        tile[ty + k * 8][tx] = res[((size_t)b * NNODE + n) * CCH + c] + xg[b * CCH + c];
    }
    __syncthreads();
    #pragma unroll
    for (int k = 0; k < 4; k++) {
        const int c = c0 + ty + k * 8;
        const int n = n0 + tx;
        out[((size_t)b * CCH + c) * NNODE + n] = tile[tx][ty + k * 8] * scale[c] + shift[c];
    }
}

// ---------------- launch ----------------
extern "C" void kernel_launch(void* const* d_in, const int* in_sizes, int n_in,
                              void* d_out, int out_size)
{
    const float* x = nullptr;
    const float* w[4] = {nullptr, nullptr, nullptr, nullptr};
    const float* v[7] = {nullptr, nullptr, nullptr, nullptr, nullptr, nullptr, nullptr};
    int wi = 0, vi = 0;
    for (int i = 0; i < n_in; i++) {
        const int sz = in_sizes[i];
        if (sz == MROWS * CCH) { if (!x) x = (const float*)d_in[i]; }
        else if (sz == CCH * CCH) { if (wi < 4) w[wi++] = (const float*)d_in[i]; }
        else if (sz == CCH) { if (vi < 7) v[vi++] = (const float*)d_in[i]; }
    }
    const float* b_pre = v[0]; const float* b_g1 = v[1]; const float* b_g2 = v[2];
    const float* g1 = v[3];    const float* beta1 = v[4];
    const float* g2 = v[5];    const float* beta2 = v[6];

    float *p_res, *p_hp, *p_rs, *p_rq, *p_xg, *p_bv, *p_sc, *p_sh;
    __nv_bfloat16 *p_xah, *p_xal, *p_h1h, *p_h1l, *p_yh, *p_yl, *p_wh, *p_wl;
    cudaGetSymbolAddress((void**)&p_res, g_res);
    cudaGetSymbolAddress((void**)&p_xah, g_xah);
    cudaGetSymbolAddress((void**)&p_xal, g_xal);
    cudaGetSymbolAddress((void**)&p_h1h, g_h1h);
    cudaGetSymbolAddress((void**)&p_h1l, g_h1l);
    cudaGetSymbolAddress((void**)&p_yh, g_yh);
    cudaGetSymbolAddress((void**)&p_yl, g_yl);
    cudaGetSymbolAddress((void**)&p_wh, g_wh);
    cudaGetSymbolAddress((void**)&p_wl, g_wl);
    cudaGetSymbolAddress((void**)&p_hp, g_hp);
    cudaGetSymbolAddress((void**)&p_rs, g_rs);
    cudaGetSymbolAddress((void**)&p_rq, g_rq);
    cudaGetSymbolAddress((void**)&p_xg, g_xg);
    cudaGetSymbolAddress((void**)&p_bv, g_bv);
    cudaGetSymbolAddress((void**)&p_sc, g_scale);
    cudaGetSymbolAddress((void**)&p_sh, g_shift);

    float* out = (float*)d_out;

    cudaFuncSetAttribute(gemm_mma<0>, cudaFuncAttributeMaxDynamicSharedMemorySize, (int)GEMM_SMEM);
    cudaFuncSetAttribute(gemm_mma<1>, cudaFuncAttributeMaxDynamicSharedMemorySize, (int)GEMM_SMEM);

    const int agg8_blocks = (MROWS * 64) / 256;   // 8192
    const size_t WB = (size_t)CCH * CCH;

    // weight prep: w_res -> blk0, w_g2 -> blk3, Wc -> blk1, bv
    convert_w_kernel<<<dim3(16, 16, 2), dim3(32, 8)>>>(w[0], w[3], p_wh, p_wl);
    wc_kernel<<<dim3(16, 16), dim3(32, 8)>>>(w[1], w[2], p_wh, p_wl);
    bv_kernel<<<2, 256>>>(b_pre, w[2], p_bv);

    // xa = Agg(x) -> split bf16
    agg_x_kernel<<<agg8_blocks, 256>>>(x, p_xah, p_xal);

    // dual GEMM: ntile 0..3 -> res = x@w_res (fp32 A, store + stats partials)
    //            ntile 4..7 -> h1 = relu(xa@Wc + s*bv + b_g1) -> split bf16
    gemm_mma<1><<<dim3(8, 256), 256, GEMM_SMEM>>>(
        x, p_xah, p_xal, p_wh, p_wl,
        p_res, nullptr, p_rs, p_rq,
        p_h1h, p_h1l, p_bv, b_g1,
        /*mode0=*/1 | 8 | 16, /*mode1=*/32);

    // ya = Agg(h1) -> split bf16
    agg_y_kernel<<<agg8_blocks, 256>>>(p_h1h, p_h1l, p_yh, p_yl);

    // h2 colsums: relu(ya@w_g2 + b_g2) -> hp partials, no store
    gemm_mma<0><<<dim3(4, 256), 256, GEMM_SMEM>>>(
        nullptr, p_yh, p_yl, p_wh + 3 * WB, p_wl + 3 * WB,
        nullptr, b_g2, p_hp, nullptr,
        nullptr, nullptr, nullptr, nullptr,
        /*mode0=*/2 | 4 | 8, /*mode1=*/0);

    bn1_kernel<<<4, 128>>>(p_hp, g1, beta1, p_xg);
    stats_reduce_kernel<<<4, 128>>>(p_rs, p_rq, p_xg, g2, beta2, p_sc, p_sh);
    final_kernel<<<dim3(NNODE / 32, CCH / 32, BATCH), dim3(32, 8)>>>(p_res, p_xg, p_sc, p_sh, out);
}